// round 13
// baseline (speedup 1.0000x reference)
#include <cuda_runtime.h>
#include <cuda_bf16.h>
#include <cuda_fp16.h>
#include <cstdint>

#define EPSV 1e-5f

// ---------------- scratch (device globals; no allocation allowed) ----------
__device__ float g_qk[32u * 256u * 1024u];   // [n][o(0..127=q,128..255=k)][l]
__device__ float g_f [32u * 9216u];          // [n][r*1024 + l], LN'd in place
__device__ float g_fp[64u * 9216u];          // kB partials [cs*32+n][r*1024+l]
__device__ float g_cpart[72u * 256u * 32u];  // [ksplit][c][n]
__device__ float g_h2[32u * 131072u];        // [n][o]
__device__ float g_dp1[2048u * 32u];
__device__ float g_dp2[2048u * 32u];
__device__ float g_stats[32u * 2u];

// fp16 split operands: A-side hi/lo, B-side single
__device__ __align__(16) __half g_wh[256u * 256u];        // [o][c]
__device__ __align__(16) __half g_wl[256u * 256u];
__device__ __align__(16) __half g_xh[32u * 1024u * 256u]; // [n][l][c]
__device__ __align__(16) __half g_h1h[32u * 256u];        // [n][c]
__device__ __align__(16) __half g_h1l[32u * 256u];
__device__ __align__(16) __half g_yh[32u * 1024u * 128u]; // [n][l][c]
__device__ __align__(16) __half g_voh[256u * 128u];       // [o][c]
__device__ __align__(16) __half g_vol[256u * 128u];

// ======================= warp-MMA helpers ==================================
__device__ __forceinline__ uint32_t smem_u32(const void* p) {
    uint32_t a;
    asm("{ .reg .u64 t; cvta.to.shared.u64 t, %1; cvt.u32.u64 %0, t; }"
        : "=r"(a) : "l"(p));
    return a;
}
__device__ __forceinline__ void ldm_x4(uint32_t* r, uint32_t addr) {
    asm volatile("ldmatrix.sync.aligned.m8n8.x4.shared.b16 {%0,%1,%2,%3}, [%4];"
                 : "=r"(r[0]), "=r"(r[1]), "=r"(r[2]), "=r"(r[3]) : "r"(addr));
}
__device__ __forceinline__ void mma_f16(float* d, const uint32_t* a,
                                        const uint32_t* b) {
    asm volatile(
        "mma.sync.aligned.m16n8k16.row.col.f32.f16.f16.f32 "
        "{%0,%1,%2,%3}, {%4,%5,%6,%7}, {%8,%9}, {%0,%1,%2,%3};"
        : "+f"(d[0]), "+f"(d[1]), "+f"(d[2]), "+f"(d[3])
        : "r"(a[0]), "r"(a[1]), "r"(a[2]), "r"(a[3]), "r"(b[0]), "r"(b[1]));
}
__device__ __forceinline__ void cpa16(uint32_t dst, const void* src) {
    asm volatile("cp.async.cg.shared.global [%0], [%1], 16;"
                 :: "r"(dst), "l"(src));
}
#define CP_COMMIT() asm volatile("cp.async.commit_group;" ::: "memory")
#define CP_WAIT1()  asm volatile("cp.async.wait_group 1;" ::: "memory")
#define CP_WAIT2()  asm volatile("cp.async.wait_group 2;" ::: "memory")

// =============== kWV: split concat(wq,wk) and w_out into fp16 hi/lo =========
__global__ void kWV(const float* __restrict__ wq, const float* __restrict__ wk,
                    const float* __restrict__ wout) {
    int idx = blockIdx.x * 256 + threadIdx.x;
    if (idx < 65536) {
        int o = idx >> 8, c = idx & 255;
        float v = (o < 128) ? wq[o * 256 + c] : wk[(o - 128) * 256 + c];
        __half hi = __float2half(v);
        g_wh[idx] = hi;
        g_wl[idx] = __float2half(v - __half2float(hi));
    } else {
        int j = idx - 65536;
        float v = wout[j];
        __half hi = __float2half(v);
        g_voh[j] = hi;
        g_vol[j] = __float2half(v - __half2float(hi));
    }
}

// ====== kT: transpose x[n][c][l] -> xT[n][l][c], single fp16 ================
__global__ void kT(const float* __restrict__ x) {
    __shared__ float tile[32][33];
    int c0 = blockIdx.x * 32, l0 = blockIdx.y * 32, n = blockIdx.z;
    int tx = threadIdx.x, ty = threadIdx.y;
    const float* xn = x + (size_t)n * 256 * 1024;
#pragma unroll
    for (int k = 0; k < 4; k++)
        tile[ty + k * 8][tx] = xn[(size_t)(c0 + ty + k * 8) * 1024 + l0 + tx];
    __syncthreads();
#pragma unroll
    for (int k = 0; k < 4; k++) {
        int l = l0 + ty + k * 8, c = c0 + tx;
        g_xh[((size_t)n * 1024 + l) * 256 + c] = __float2half(tile[tx][ty + k * 8]);
    }
}

// ====== kA2: qk = W @ x, fp16 2-term (Wh+Wl)*xh, cp.async 3-stage ==========
#define ASTR 40
#define TILE_B 10240                        // one 128xASTR fp16 tile bytes
#define BUF_B  (3 * TILE_B)                 // Ah, Al, Bh per stage
#define OFFAH 0
#define OFFAL TILE_B
#define OFFBH (2 * TILE_B)
__global__ void __launch_bounds__(256, 2) kA2() {
    extern __shared__ char dsm[];
    uint32_t sb = smem_u32(dsm);

    int t = threadIdx.x, lane = t & 31, wid = t >> 5;
    int warp_m = wid & 3, warp_n = wid >> 2;
    int lt = blockIdx.x, ot = blockIdx.y, n = blockIdx.z;

    float acc[2][8][4];
#pragma unroll
    for (int i = 0; i < 2; i++)
#pragma unroll
        for (int j = 0; j < 8; j++)
#pragma unroll
            for (int kq = 0; kq < 4; kq++) acc[i][j][kq] = 0.f;

    int a_row = warp_m * 32 + (lane & 15);
    int a_koff = (lane >> 4) * 8;
    int b_row = warp_n * 64 + (lane & 7) + ((lane >> 4) & 1) * 8;
    int b_koff = ((lane >> 3) & 1) * 8;

    int r = t >> 2, q = t & 3;
    uint32_t so = (uint32_t)(r * ASTR + q * 8) * 2;
    uint32_t so2 = (uint32_t)((r + 64) * ASTR + q * 8) * 2;

    auto issue = [&](int buf, int chunk) {
        uint32_t base = sb + buf * BUF_B;
        int acol = chunk * 32;
        size_t goA = (size_t)(ot * 128 + r) * 256 + acol + q * 8;
        cpa16(base + OFFAH + so, g_wh + goA);
        cpa16(base + OFFAL + so, g_wl + goA);
        cpa16(base + OFFAH + so2, g_wh + goA + 64 * 256);
        cpa16(base + OFFAL + so2, g_wl + goA + 64 * 256);
        size_t goB = ((size_t)n * 1024 + lt * 128 + r) * 256 + acol + q * 8;
        cpa16(base + OFFBH + so, g_xh + goB);
        cpa16(base + OFFBH + so2, g_xh + goB + 64 * 256);
        CP_COMMIT();
    };

    issue(0, 0); issue(1, 1);
    int buf = 0;
    for (int chunk = 0; chunk < 8; chunk++) {
        CP_WAIT1();
        __syncthreads();
        if (chunk + 2 < 8) {
            int nb = buf + 2; if (nb >= 3) nb -= 3;
            issue(nb, chunk + 2);
        } else CP_COMMIT();
        uint32_t base = sb + buf * BUF_B;
        uint32_t sAh = base + OFFAH, sAl = base + OFFAL, sBh = base + OFFBH;

#pragma unroll
        for (int ks = 0; ks < 2; ks++) {
            uint32_t ah[2][4], al[2][4];
#pragma unroll
            for (int im = 0; im < 2; im++) {
                uint32_t off = ((a_row + im * 16) * ASTR + ks * 16 + a_koff) * 2;
                ldm_x4(ah[im], sAh + off);
                ldm_x4(al[im], sAl + off);
            }
            uint32_t bh[4][4];
#pragma unroll
            for (int jn = 0; jn < 4; jn++) {
                uint32_t off = ((b_row + jn * 16) * ASTR + ks * 16 + b_koff) * 2;
                ldm_x4(bh[jn], sBh + off);
            }
#pragma unroll
            for (int im = 0; im < 2; im++)
#pragma unroll
                for (int jb = 0; jb < 8; jb++) {
                    const uint32_t* ph = bh[jb >> 1] + (jb & 1) * 2;
                    mma_f16(acc[im][jb], ah[im], ph);
                    mma_f16(acc[im][jb], al[im], ph);
                }
        }
        if (++buf >= 3) buf = 0;
    }

    int g = lane >> 2, t4 = lane & 3;
#pragma unroll
    for (int im = 0; im < 2; im++) {
        int o0 = ot * 128 + warp_m * 32 + im * 16 + g;
#pragma unroll
        for (int jb = 0; jb < 8; jb++) {
            int l = lt * 128 + warp_n * 64 + jb * 8 + t4 * 2;
            float* p0 = g_qk + ((size_t)n * 256 + o0) * 1024 + l;
            float* p1 = g_qk + ((size_t)n * 256 + o0 + 8) * 1024 + l;
            p0[0] = acc[im][jb][0]; p0[1] = acc[im][jb][1];
            p1[0] = acc[im][jb][2]; p1[1] = acc[im][jb][3];
        }
    }
}

// ============ Kernel B: partial f over 64-channel chunk =====================
// grid (32 h, 32 n, 2 cs); float4-packed channels (c, c+16, c+32, c+48)
// within the 64-channel group. Single load/sync/compute phase.
__global__ void kB() {
    int h = blockIdx.x, n = blockIdx.y, cs = blockIdx.z;
    __shared__ float4 qs[16][32];    // 8 KB
    __shared__ float4 ks[16][102];   // 25.5 KB
    int t = threadIdx.x;
    int r = t >> 5, w = t & 31;
    int c0 = cs * 64;
    const float* qn = g_qk + (size_t)n * 256 * 1024;
    const float* kn = qn + 128u * 1024u;
    int hh = r / 3, dw = r % 3;
    int kidx = hh * 34 + w + dw;

    for (int idx = t; idx < 16 * 32; idx += 288) {
        int cc = idx >> 5, ww = idx & 31;
        const float* b = qn + (size_t)(c0 + cc) * 1024 + h * 32 + ww;
        qs[cc][ww] = make_float4(b[0], b[16 * 1024], b[32 * 1024], b[48 * 1024]);
    }
    for (int idx = t; idx < 16 * 102; idx += 288) {
        int cc = idx / 102, rem = idx % 102;
        int rr = rem / 34, ww = rem % 34;
        int hg = h + rr - 1, wg = ww - 1;
        float4 v = make_float4(0.f, 0.f, 0.f, 0.f);
        if (hg >= 0 && hg < 32 && wg >= 0 && wg < 32) {
            const float* b = kn + (size_t)(c0 + cc) * 1024 + hg * 32 + wg;
            v = make_float4(b[0], b[16 * 1024], b[32 * 1024], b[48 * 1024]);
        }
        ks[cc][rem] = v;
    }
    __syncthreads();
    float a0 = 0.f, a1 = 0.f, a2 = 0.f, a3 = 0.f;
#pragma unroll
    for (int cc = 0; cc < 16; cc++) {
        float4 qv = qs[cc][w];
        float4 kv = ks[cc][kidx];
        a0 += qv.x * kv.x;
        a1 += qv.y * kv.y;
        a2 += qv.z * kv.z;
        a3 += qv.w * kv.w;
    }
    g_fp[(size_t)(cs * 32 + n) * 9216 + r * 1024 + h * 32 + w] =
        (a0 + a1) + (a2 + a3);
}

// ========== Kernel B2: combine partials, x2, layernorm -> g_f ===============
__global__ void kB2(const float* __restrict__ g1, const float* __restrict__ be1) {
    int n = blockIdx.x;
    const float* p0 = g_fp + (size_t)n * 9216;
    const float* p1 = g_fp + (size_t)(32 + n) * 9216;
    float* f = g_f + (size_t)n * 9216;
    float s = 0.f, q = 0.f;
    for (int j = threadIdx.x; j < 9216; j += 256) {
        float v = 2.f * (p0[j] + p1[j]);
        f[j] = v;
        s += v; q += v * v;
    }
#pragma unroll
    for (int off = 16; off; off >>= 1) {
        s += __shfl_down_sync(0xFFFFFFFFu, s, off);
        q += __shfl_down_sync(0xFFFFFFFFu, q, off);
    }
    __shared__ float sh[34];
    int wv = threadIdx.x >> 5, lane = threadIdx.x & 31;
    if (lane == 0) { sh[wv] = s; sh[wv + 8] = q; }
    __syncthreads();
    if (threadIdx.x == 0) {
        float S = 0.f, Q = 0.f;
        for (int i = 0; i < 8; i++) { S += sh[i]; Q += sh[i + 8]; }
        float mu = S / 9216.f;
        float var = Q / 9216.f - mu * mu;
        sh[32] = mu;
        sh[33] = rsqrtf(var + EPSV);
    }
    __syncthreads();
    float mu = sh[32], rstd = sh[33];
    for (int j = threadIdx.x; j < 9216; j += 256)
        f[j] = (f[j] - mu) * rstd * g1[j] + be1[j];
}

// ===== Kernel C: split-K tiled GEMM: h1[n,c] partials, 72 K-slices ==========
__global__ void kC(const float* __restrict__ w1) {
    __shared__ float fs[32][33];
    __shared__ float ws[32][65];
    int ct = blockIdx.x, sp = blockIdx.y;
    int t = threadIdx.x;
    int tn = t & 15, tc = t >> 4;
    float acc[2][4];
#pragma unroll
    for (int i = 0; i < 2; i++)
#pragma unroll
        for (int j = 0; j < 4; j++) acc[i][j] = 0.f;

    int j0 = sp * 128;
    for (int k0 = j0; k0 < j0 + 128; k0 += 32) {
        __syncthreads();
#pragma unroll
        for (int i = 0; i < 4; i++) {
            int idx = t + i * 256;
            int n = idx >> 5, kk = idx & 31;
            fs[kk][n] = g_f[(size_t)n * 9216 + k0 + kk];
        }
#pragma unroll
        for (int i = 0; i < 8; i++) {
            int idx = t + i * 256;
            int c = idx >> 5, kk = idx & 31;
            ws[kk][c] = w1[(size_t)(ct * 64 + c) * 9216 + k0 + kk];
        }
        __syncthreads();
#pragma unroll
        for (int kk = 0; kk < 32; kk++) {
            float fv[2], wv[4];
            fv[0] = fs[kk][tn * 2];
            fv[1] = fs[kk][tn * 2 + 1];
#pragma unroll
            for (int j = 0; j < 4; j++) wv[j] = ws[kk][tc * 4 + j];
#pragma unroll
            for (int i = 0; i < 2; i++)
#pragma unroll
                for (int j = 0; j < 4; j++) acc[i][j] += fv[i] * wv[j];
        }
    }
#pragma unroll
    for (int i = 0; i < 2; i++)
#pragma unroll
        for (int j = 0; j < 4; j++)
            g_cpart[(size_t)(sp * 256 + ct * 64 + tc * 4 + j) * 32 + tn * 2 + i] =
                acc[i][j];
}

// -------- Kernel C2: reduce splits, bias, relu, split to fp16 [n][c] --------
__global__ void kC2(const float* __restrict__ b1) {
    int idx = blockIdx.x * 256 + threadIdx.x;  // 8192 = 256c * 32n
    int c = idx >> 5, n = idx & 31;
    float a = b1[c];
#pragma unroll
    for (int sp = 0; sp < 72; sp++) a += g_cpart[(size_t)(sp * 256 + c) * 32 + n];
    a = fmaxf(a, 0.f);
    __half hi = __float2half(a);
    g_h1h[n * 256 + c] = hi;
    g_h1l[n * 256 + c] = __float2half(a - __half2float(hi));
}

// ====== kD_mma: h2 = h1 @ w2^T; fp16 2-term; 4-deep cp.async w2 ring ========
#define WSTR 36
#define BSTR 40
#define KD_WST 0                              // 4 x 128 x WSTR fp32 = 73728 B
#define KD_AH  73728                          // 32 x BSTR fp16 = 2560 B
#define KD_AL  (KD_AH + 2560)
#define KD_BH  (KD_AL + 2560)                 // 128 x BSTR fp16 = 10240 B
#define KD_SM  (KD_BH + 10240)
#define KD_SMEM (KD_SM + 256)
__global__ void __launch_bounds__(256, 2) kD_mma(const float* __restrict__ w2,
                                                 const float* __restrict__ b2) {
    extern __shared__ char dsm[];
    uint32_t sb = smem_u32(dsm);
    float* Wst = (float*)dsm;
    __half* Bh = (__half*)(dsm + KD_BH);
    __half* Ah = (__half*)(dsm + KD_AH);
    __half* Al = (__half*)(dsm + KD_AL);
    float* sm1 = (float*)(dsm + KD_SM);
    float* sm2 = sm1 + 32;

    int t = threadIdx.x, lane = t & 31, wid = t >> 5;
    int bo = blockIdx.x * 128;
    if (t < 32) { sm1[t] = 0.f; sm2[t] = 0.f; }

    float acc[2][2][4];
#pragma unroll
    for (int i = 0; i < 2; i++)
#pragma unroll
        for (int j = 0; j < 2; j++)
#pragma unroll
            for (int kq = 0; kq < 4; kq++) acc[i][j][kq] = 0.f;

    uint32_t sAh = sb + KD_AH, sAl = sb + KD_AL, sBh = sb + KD_BH;

    int a_row = lane & 15;
    int a_koff = (lane >> 4) * 8;
    int b_row = wid * 16 + (lane & 7) + ((lane >> 4) & 1) * 8;
    int b_koff = ((lane >> 3) & 1) * 8;

    auto issueW = [&](int buf, int chunk) {
#pragma unroll
        for (int i = 0; i < 4; i++) {
            int idx = t + i * 256;
            int r = idx >> 3, q = idx & 7;
            cpa16(sb + KD_WST + (uint32_t)(buf * 128 * WSTR + r * WSTR + q * 4) * 4,
                  w2 + (size_t)(bo + r) * 256 + chunk * 32 + q * 4);
        }
        CP_COMMIT();
    };

    issueW(0, 0); issueW(1, 1); issueW(2, 2);
    for (int chunk = 0; chunk < 8; chunk++) {
        int k0 = chunk * 32;
        CP_WAIT2();
        __syncthreads();
        if (chunk + 3 < 8) issueW((chunk + 3) & 3, chunk + 3);
        else CP_COMMIT();                      // keep FIFO group count exact
        // A: 32 rows x 32 fp16 per split
        if (t < 128) {
            int r = t >> 2, q = t & 3;
            *(uint4*)&Ah[r * BSTR + q * 8] = *(const uint4*)&g_h1h[r * 256 + k0 + q * 8];
            *(uint4*)&Al[r * BSTR + q * 8] = *(const uint4*)&g_h1l[r * 256 + k0 + q * 8];
        }
        // convert staged fp32 w2 -> fp16 Bh
        const float* Wb = Wst + (chunk & 3) * 128 * WSTR;
#pragma unroll
        for (int i = 0; i < 4; i++) {
            int idx = t + i * 256;
            int r = idx >> 3, q = idx & 7;
            float4 v = *(const float4*)&Wb[r * WSTR + q * 4];
            __half2 p01 = __floats2half2_rn(v.x, v.y);
            __half2 p23 = __floats2half2_rn(v.z, v.w);
            *(uint2*)&Bh[r * BSTR + q * 4] =
                make_uint2(*(uint32_t*)&p01, *(uint32_t*)&p23);
        }
        __syncthreads();

#pragma unroll
        for (int ks = 0; ks < 2; ks++) {
            uint32_t ah[2][4], al[2][4];
#pragma unroll
            for (int im = 0; im < 2; im++) {
                uint32_t off = ((a_row + im * 16) * BSTR + ks * 16 + a_koff) * 2;
                ldm_x4(ah[im], sAh + off);
                ldm_x4(al[im], sAl + off);
            }
            uint32_t bh[4];
            {
                uint32_t off = (b_row * BSTR + ks * 16 + b_koff) * 2;
                ldm_x4(bh, sBh + off);
            }
#pragma unroll
            for (int im = 0; im < 2; im++)
#pragma unroll
                for (int j = 0; j < 2; j++) {
                    const uint32_t* ph = bh + j * 2;
                    mma_f16(acc[im][j], ah[im], ph);
                    mma_f16(acc[im][j], al[im], ph);
                }
        }
    }

    int g = lane >> 2, t4 = lane & 3;
#pragma unroll
    for (int j = 0; j < 2; j++) {
        int o = bo + wid * 16 + j * 8 + t4 * 2;
        float bb0 = b2[o], bb1 = b2[o + 1];
#pragma unroll
        for (int im = 0; im < 2; im++) {
            int n0 = im * 16 + g, n1 = n0 + 8;
            float v0 = acc[im][j][0] + bb0, v1 = acc[im][j][1] + bb1;
            float v2 = acc[im][j][2] + bb0, v3 = acc[im][j][3] + bb1;
            *(float2*)&g_h2[(size_t)n0 * 131072 + o] = make_float2(v0, v1);
            *(float2*)&g_h2[(size_t)n1 * 131072 + o] = make_float2(v2, v3);
            atomicAdd(&sm1[n0], v0 + v1);
            atomicAdd(&sm2[n0], v0 * v0 + v1 * v1);
            atomicAdd(&sm1[n1], v2 + v3);
            atomicAdd(&sm2[n1], v2 * v2 + v3 * v3);
        }
    }
    __syncthreads();
    if (t < 32) {
        g_dp1[(size_t)blockIdx.x * 32 + t] = sm1[t];
        g_dp2[(size_t)blockIdx.x * 32 + t] = sm2[t];
    }
}

// ---------------- Kernel D2: finish LN stats over 131072/row ----------------
__global__ void kD2() {
    int n = blockIdx.x;
    float s = 0.f, q = 0.f;
    for (int b = threadIdx.x; b < 1024; b += 256) {
        s += g_dp1[(size_t)b * 32 + n];
        q += g_dp2[(size_t)b * 32 + n];
    }
#pragma unroll
    for (int off = 16; off; off >>= 1) {
        s += __shfl_down_sync(0xFFFFFFFFu, s, off);
        q += __shfl_down_sync(0xFFFFFFFFu, q, off);
    }
    __shared__ float sh[16];
    int wv = threadIdx.x >> 5, lane = threadIdx.x & 31;
    if (lane == 0) { sh[wv] = s; sh[wv + 8] = q; }
    __syncthreads();
    if (threadIdx.x == 0) {
        float S = 0.f, Q = 0.f;
        for (int i = 0; i < 8; i++) { S += sh[i]; Q += sh[i + 8]; }
        float mu = S / 131072.f;
        float var = Q / 131072.f - mu * mu;
        g_stats[n * 2] = mu;
        g_stats[n * 2 + 1] = rsqrtf(var + EPSV);
    }
}

// ====== kE0: y = LN(h2) transposed [n][l][c], single fp16 ===================
__global__ void kE0(const float* __restrict__ g2, const float* __restrict__ be2) {
    __shared__ float tile[32][33];
    int c0 = blockIdx.x * 32, l0 = blockIdx.y * 32, n = blockIdx.z;
    int tx = threadIdx.x, ty = threadIdx.y;
    float mu = g_stats[n * 2], rstd = g_stats[n * 2 + 1];
    const float* h2n = g_h2 + (size_t)n * 131072;
#pragma unroll
    for (int k = 0; k < 4; k++) {
        int gidx = (c0 + ty + k * 8) * 1024 + l0 + tx;
        tile[ty + k * 8][tx] = (h2n[gidx] - mu) * rstd * g2[gidx] + be2[gidx];
    }
    __syncthreads();
#pragma unroll
    for (int k = 0; k < 4; k++) {
        int l = l0 + ty + k * 8, c = c0 + tx;
        g_yh[((size_t)n * 1024 + l) * 128 + c] = __float2half(tile[tx][ty + k * 8]);
    }
}

// ====== kE_mma: out = BN(w_out @ y) + x; fp16 2-term; cp.async 3-stage ======
__global__ void __launch_bounds__(256, 2) kE_mma(
    const float* __restrict__ bng, const float* __restrict__ bnb,
    const float* __restrict__ bnm, const float* __restrict__ bnv,
    const float* __restrict__ x, float* __restrict__ out) {
    extern __shared__ char dsm[];
    uint32_t sb = smem_u32(dsm);

    int t = threadIdx.x, lane = t & 31, wid = t >> 5;
    int warp_m = wid & 3, warp_n = wid >> 2;
    int lt = blockIdx.x, ot = blockIdx.y, n = blockIdx.z;

    float acc[2][8][4];
#pragma unroll
    for (int i = 0; i < 2; i++)
#pragma unroll
        for (int j = 0; j < 8; j++)
#pragma unroll
            for (int kq = 0; kq < 4; kq++) acc[i][j][kq] = 0.f;

    int a_row = warp_m * 32 + (lane & 15);
    int a_koff = (lane >> 4) * 8;
    int b_row = warp_n * 64 + (lane & 7) + ((lane >> 4) & 1) * 8;
    int b_koff = ((lane >> 3) & 1) * 8;

    int r = t >> 2, q = t & 3;
    uint32_t so = (uint32_t)(r * ASTR + q * 8) * 2;
    uint32_t so2 = (uint32_t)((r + 64) * ASTR + q * 8) * 2;

    auto issue = [&](int buf, int chunk) {
        uint32_t base = sb + buf * BUF_B;
        int acol = chunk * 32;
        size_t goA = (size_t)(ot * 128 + r) * 128 + acol + q * 8;
        cpa16(base + OFFAH + so, g_voh + goA);
        cpa16(base + OFFAL + so, g_vol + goA);
        cpa16(base + OFFAH + so2, g_voh + goA + 64 * 128);
        cpa16(base + OFFAL + so2, g_vol + goA + 64 * 128);
        size_t goB = ((size_t)n * 1024 + lt * 128 + r) * 128 + acol + q * 8;
        cpa16(base + OFFBH + so, g_yh + goB);
        cpa16(base + OFFBH + so2, g_yh + goB + 64 * 128);
        CP_COMMIT();
    };

    issue(0, 0); issue(1, 1);
    int buf = 0;
    for (int chunk = 0; chunk < 4; chunk++) {
        CP_WAIT1();
        __syncthreads();
        if (chunk + 2 < 4) {
            int nb = buf + 2; if (nb >= 3) nb -= 3;
            issue(nb, chunk + 2);
        } else CP_COMMIT();
        uint32_t base = sb + buf * BUF_B;
        uint32_t sAh = base + OFFAH, sAl = base + OFFAL, sBh = base + OFFBH;

#pragma unroll
        for (int ks = 0; ks < 2; ks++) {
            uint32_t ah[2][4], al[2][4];
#pragma unroll
            for (int im = 0; im < 2; im++) {
                uint32_t off = ((a_row + im * 16) * ASTR + ks * 16 + a_koff) * 2;
                ldm_x4(ah[im], sAh + off);
                ldm_x4(al[im], sAl + off);
            }
            uint32_t bh[4][4];
#pragma unroll
            for (int jn = 0; jn < 4; jn++) {
                uint32_t off = ((b_row + jn * 16) * ASTR + ks * 16 + b_koff) * 2;
                ldm_x4(bh[jn], sBh + off);
            }
#pragma unroll
            for (int im = 0; im < 2; im++)
#pragma unroll
                for (int jb = 0; jb < 8; jb++) {
                    const uint32_t* ph = bh[jb >> 1] + (jb & 1) * 2;
                    mma_f16(acc[im][jb], ah[im], ph);
                    mma_f16(acc[im][jb], al[im], ph);
                }
        }
        if (++buf >= 3) buf = 0;
    }

    int g = lane >> 2, t4 = lane & 3;
#pragma unroll
    for (int im = 0; im < 2; im++) {
        int oa = ot * 128 + warp_m * 32 + im * 16 + g;
        int ob = oa + 8;
        float scA = bng[oa] * rsqrtf(bnv[oa] + EPSV);
        float scB = bng[ob] * rsqrtf(bnv[ob] + EPSV);
        float mbA = bnm[oa], bbA = bnb[oa];
        float mbB = bnm[ob], bbB = bnb[ob];
        const float* xa = x + ((size_t)n * 256 + oa) * 1024;
        const float* xb = x + ((size_t)n * 256 + ob) * 1024;
        float* pa = out + ((size_t)n * 256 + oa) * 1024;
        float* pb = out + ((size_t)n * 256 + ob) * 1024;
#pragma unroll
        for (int jb = 0; jb < 8; jb++) {
            int l = lt * 128 + warp_n * 64 + jb * 8 + t4 * 2;
            float2 xva = *(const float2*)&xa[l];
            float2 xvb = *(const float2*)&xb[l];
            float2 ra, rb;
            ra.x = (acc[im][jb][0] - mbA) * scA + bbA + xva.x;
            ra.y = (acc[im][jb][1] - mbA) * scA + bbA + xva.y;
            rb.x = (acc[im][jb][2] - mbB) * scB + bbB + xvb.x;
            rb.y = (acc[im][jb][3] - mbB) * scB + bbB + xvb.y;
            *(float2*)&pa[l] = ra;
            *(float2*)&pb[l] = rb;
        }
    }
}

// ============================== launcher ====================================
extern "C" void kernel_launch(void* const* d_in, const int* in_sizes, int n_in,
                              void* d_out, int out_size) {
    const float* x    = (const float*)d_in[0];
    const float* wq   = (const float*)d_in[1];
    const float* wk   = (const float*)d_in[2];
    const float* g1   = (const float*)d_in[3];
    const float* be1  = (const float*)d_in[4];
    const float* w1   = (const float*)d_in[5];
    const float* b1   = (const float*)d_in[6];
    const float* w2   = (const float*)d_in[7];
    const float* b2   = (const float*)d_in[8];
    const float* g2   = (const float*)d_in[9];
    const float* be2  = (const float*)d_in[10];
    const float* wout = (const float*)d_in[11];
    const float* bng  = (const float*)d_in[12];
    const float* bnb  = (const float*)d_in[13];
    const float* bnm  = (const float*)d_in[14];
    const float* bnv  = (const float*)d_in[15];
    float* out = (float*)d_out;

    static bool attr_done = false;
    if (!attr_done) {
        cudaFuncSetAttribute(kA2, cudaFuncAttributeMaxDynamicSharedMemorySize,
                             3 * BUF_B);
        cudaFuncSetAttribute(kE_mma, cudaFuncAttributeMaxDynamicSharedMemorySize,
                             3 * BUF_B);
        cudaFuncSetAttribute(kD_mma, cudaFuncAttributeMaxDynamicSharedMemorySize,
                             KD_SMEM);
        attr_done = true;
    }

    kWV<<<384, 256>>>(wq, wk, wout);
    kT<<<dim3(8, 32, 32), dim3(32, 8)>>>(x);
    kA2<<<dim3(8, 2, 32), 256, 3 * BUF_B>>>();
    kB<<<dim3(32, 32, 2), 288>>>();
    kB2<<<32, 256>>>(g1, be1);
    kC<<<dim3(4, 72), 256>>>(w1);
    kC2<<<32, 256>>>(b1);
    kD_mma<<<1024, 256, KD_SMEM>>>(w2, b2);
    kD2<<<32, 256>>>();
    kE0<<<dim3(4, 32, 32), dim3(32, 8)>>>(g2, be2);
    kE_mma<<<dim3(8, 2, 32), 256, 3 * BUF_B>>>(bng, bnb, bnm, bnv, x, out);
}

// round 14
// speedup vs baseline: 1.0446x; 1.0446x over previous
#include <cuda_runtime.h>
#include <cuda_bf16.h>
#include <cuda_fp16.h>
#include <cstdint>

#define EPSV 1e-5f

// ---------------- scratch (device globals; no allocation allowed) ----------
__device__ float g_qk[32u * 256u * 1024u];   // [n][o(0..127=q,128..255=k)][l]
__device__ float g_f [32u * 9216u];          // [n][r*1024 + l]; kB accumulates
__device__ float g_cpart[72u * 256u * 32u];  // [ksplit][c][n]
__device__ float g_h2[32u * 131072u];        // [n][o]
__device__ float g_dp1[2048u * 32u];
__device__ float g_dp2[2048u * 32u];
__device__ float g_stats[32u * 2u];

// fp16 split operands: A-side hi/lo, B-side single
__device__ __align__(16) __half g_wh[256u * 256u];        // [o][c]
__device__ __align__(16) __half g_wl[256u * 256u];
__device__ __align__(16) __half g_xh[32u * 1024u * 256u]; // [n][l][c]
__device__ __align__(16) __half g_h1h[32u * 256u];        // [n][c]
__device__ __align__(16) __half g_h1l[32u * 256u];
__device__ __align__(16) __half g_yh[32u * 1024u * 128u]; // [n][l][c]
__device__ __align__(16) __half g_voh[256u * 128u];       // [o][c]
__device__ __align__(16) __half g_vol[256u * 128u];

// ======================= warp-MMA helpers ==================================
__device__ __forceinline__ uint32_t smem_u32(const void* p) {
    uint32_t a;
    asm("{ .reg .u64 t; cvta.to.shared.u64 t, %1; cvt.u32.u64 %0, t; }"
        : "=r"(a) : "l"(p));
    return a;
}
__device__ __forceinline__ void ldm_x4(uint32_t* r, uint32_t addr) {
    asm volatile("ldmatrix.sync.aligned.m8n8.x4.shared.b16 {%0,%1,%2,%3}, [%4];"
                 : "=r"(r[0]), "=r"(r[1]), "=r"(r[2]), "=r"(r[3]) : "r"(addr));
}
__device__ __forceinline__ void mma_f16(float* d, const uint32_t* a,
                                        const uint32_t* b) {
    asm volatile(
        "mma.sync.aligned.m16n8k16.row.col.f32.f16.f16.f32 "
        "{%0,%1,%2,%3}, {%4,%5,%6,%7}, {%8,%9}, {%0,%1,%2,%3};"
        : "+f"(d[0]), "+f"(d[1]), "+f"(d[2]), "+f"(d[3])
        : "r"(a[0]), "r"(a[1]), "r"(a[2]), "r"(a[3]), "r"(b[0]), "r"(b[1]));
}
__device__ __forceinline__ void cpa16(uint32_t dst, const void* src) {
    asm volatile("cp.async.cg.shared.global [%0], [%1], 16;"
                 :: "r"(dst), "l"(src));
}
#define CP_COMMIT() asm volatile("cp.async.commit_group;" ::: "memory")
#define CP_WAIT1()  asm volatile("cp.async.wait_group 1;" ::: "memory")
#define CP_WAIT2()  asm volatile("cp.async.wait_group 2;" ::: "memory")

// ==== kWV: split concat(wq,wk)+w_out into fp16 hi/lo; zero g_f ==============
__global__ void kWV(const float* __restrict__ wq, const float* __restrict__ wk,
                    const float* __restrict__ wout) {
    int idx = blockIdx.x * 256 + threadIdx.x;   // 98304 threads
    if (idx < 65536) {
        int o = idx >> 8, c = idx & 255;
        float v = (o < 128) ? wq[o * 256 + c] : wk[(o - 128) * 256 + c];
        __half hi = __float2half(v);
        g_wh[idx] = hi;
        g_wl[idx] = __float2half(v - __half2float(hi));
    } else {
        int j = idx - 65536;
        float v = wout[j];
        __half hi = __float2half(v);
        g_voh[j] = hi;
        g_vol[j] = __float2half(v - __half2float(hi));
    }
    g_f[idx] = 0.f;
    g_f[idx + 98304] = 0.f;
    g_f[idx + 196608] = 0.f;
}

// ====== kT: transpose x[n][c][l] -> xT[n][l][c], single fp16 ================
__global__ void kT(const float* __restrict__ x) {
    __shared__ float tile[32][33];
    int c0 = blockIdx.x * 32, l0 = blockIdx.y * 32, n = blockIdx.z;
    int tx = threadIdx.x, ty = threadIdx.y;
    const float* xn = x + (size_t)n * 256 * 1024;
#pragma unroll
    for (int k = 0; k < 4; k++)
        tile[ty + k * 8][tx] = xn[(size_t)(c0 + ty + k * 8) * 1024 + l0 + tx];
    __syncthreads();
#pragma unroll
    for (int k = 0; k < 4; k++) {
        int l = l0 + ty + k * 8, c = c0 + tx;
        g_xh[((size_t)n * 1024 + l) * 256 + c] = __float2half(tile[tx][ty + k * 8]);
    }
}

// ====== kA2: qk = W @ x, fp16 2-term (Wh+Wl)*xh, cp.async 3-stage ==========
#define ASTR 40
#define TILE_B 10240                        // one 128xASTR fp16 tile bytes
#define BUF_B  (3 * TILE_B)                 // Ah, Al, Bh per stage
#define OFFAH 0
#define OFFAL TILE_B
#define OFFBH (2 * TILE_B)
__global__ void __launch_bounds__(256, 2) kA2() {
    extern __shared__ char dsm[];
    uint32_t sb = smem_u32(dsm);

    int t = threadIdx.x, lane = t & 31, wid = t >> 5;
    int warp_m = wid & 3, warp_n = wid >> 2;
    int lt = blockIdx.x, ot = blockIdx.y, n = blockIdx.z;

    float acc[2][8][4];
#pragma unroll
    for (int i = 0; i < 2; i++)
#pragma unroll
        for (int j = 0; j < 8; j++)
#pragma unroll
            for (int kq = 0; kq < 4; kq++) acc[i][j][kq] = 0.f;

    int a_row = warp_m * 32 + (lane & 15);
    int a_koff = (lane >> 4) * 8;
    int b_row = warp_n * 64 + (lane & 7) + ((lane >> 4) & 1) * 8;
    int b_koff = ((lane >> 3) & 1) * 8;

    int r = t >> 2, q = t & 3;
    uint32_t so = (uint32_t)(r * ASTR + q * 8) * 2;
    uint32_t so2 = (uint32_t)((r + 64) * ASTR + q * 8) * 2;

    auto issue = [&](int buf, int chunk) {
        uint32_t base = sb + buf * BUF_B;
        int acol = chunk * 32;
        size_t goA = (size_t)(ot * 128 + r) * 256 + acol + q * 8;
        cpa16(base + OFFAH + so, g_wh + goA);
        cpa16(base + OFFAL + so, g_wl + goA);
        cpa16(base + OFFAH + so2, g_wh + goA + 64 * 256);
        cpa16(base + OFFAL + so2, g_wl + goA + 64 * 256);
        size_t goB = ((size_t)n * 1024 + lt * 128 + r) * 256 + acol + q * 8;
        cpa16(base + OFFBH + so, g_xh + goB);
        cpa16(base + OFFBH + so2, g_xh + goB + 64 * 256);
        CP_COMMIT();
    };

    issue(0, 0); issue(1, 1);
    int buf = 0;
    for (int chunk = 0; chunk < 8; chunk++) {
        CP_WAIT1();
        __syncthreads();
        if (chunk + 2 < 8) {
            int nb = buf + 2; if (nb >= 3) nb -= 3;
            issue(nb, chunk + 2);
        } else CP_COMMIT();
        uint32_t base = sb + buf * BUF_B;
        uint32_t sAh = base + OFFAH, sAl = base + OFFAL, sBh = base + OFFBH;

#pragma unroll
        for (int ks = 0; ks < 2; ks++) {
            uint32_t ah[2][4], al[2][4];
#pragma unroll
            for (int im = 0; im < 2; im++) {
                uint32_t off = ((a_row + im * 16) * ASTR + ks * 16 + a_koff) * 2;
                ldm_x4(ah[im], sAh + off);
                ldm_x4(al[im], sAl + off);
            }
            uint32_t bh[4][4];
#pragma unroll
            for (int jn = 0; jn < 4; jn++) {
                uint32_t off = ((b_row + jn * 16) * ASTR + ks * 16 + b_koff) * 2;
                ldm_x4(bh[jn], sBh + off);
            }
#pragma unroll
            for (int im = 0; im < 2; im++)
#pragma unroll
                for (int jb = 0; jb < 8; jb++) {
                    const uint32_t* ph = bh[jb >> 1] + (jb & 1) * 2;
                    mma_f16(acc[im][jb], ah[im], ph);
                    mma_f16(acc[im][jb], al[im], ph);
                }
        }
        if (++buf >= 3) buf = 0;
    }

    int g = lane >> 2, t4 = lane & 3;
#pragma unroll
    for (int im = 0; im < 2; im++) {
        int o0 = ot * 128 + warp_m * 32 + im * 16 + g;
#pragma unroll
        for (int jb = 0; jb < 8; jb++) {
            int l = lt * 128 + warp_n * 64 + jb * 8 + t4 * 2;
            float* p0 = g_qk + ((size_t)n * 256 + o0) * 1024 + l;
            float* p1 = g_qk + ((size_t)n * 256 + o0 + 8) * 1024 + l;
            p0[0] = acc[im][jb][0]; p0[1] = acc[im][jb][1];
            p1[0] = acc[im][jb][2]; p1[1] = acc[im][jb][3];
        }
    }
}

// ============ Kernel B: partial f over 64-channel chunk, REDG into g_f ======
// grid (32 h, 32 n, 2 cs); float4-packed channels (c, c+16, c+32, c+48).
__global__ void kB() {
    int h = blockIdx.x, n = blockIdx.y, cs = blockIdx.z;
    __shared__ float4 qs[16][32];    // 8 KB
    __shared__ float4 ks[16][102];   // 25.5 KB
    int t = threadIdx.x;
    int r = t >> 5, w = t & 31;
    int c0 = cs * 64;
    const float* qn = g_qk + (size_t)n * 256 * 1024;
    const float* kn = qn + 128u * 1024u;
    int hh = r / 3, dw = r % 3;
    int kidx = hh * 34 + w + dw;

    for (int idx = t; idx < 16 * 32; idx += 288) {
        int cc = idx >> 5, ww = idx & 31;
        const float* b = qn + (size_t)(c0 + cc) * 1024 + h * 32 + ww;
        qs[cc][ww] = make_float4(b[0], b[16 * 1024], b[32 * 1024], b[48 * 1024]);
    }
    for (int idx = t; idx < 16 * 102; idx += 288) {
        int cc = idx / 102, rem = idx % 102;
        int rr = rem / 34, ww = rem % 34;
        int hg = h + rr - 1, wg = ww - 1;
        float4 v = make_float4(0.f, 0.f, 0.f, 0.f);
        if (hg >= 0 && hg < 32 && wg >= 0 && wg < 32) {
            const float* b = kn + (size_t)(c0 + cc) * 1024 + hg * 32 + wg;
            v = make_float4(b[0], b[16 * 1024], b[32 * 1024], b[48 * 1024]);
        }
        ks[cc][rem] = v;
    }
    __syncthreads();
    float a0 = 0.f, a1 = 0.f, a2 = 0.f, a3 = 0.f;
#pragma unroll
    for (int cc = 0; cc < 16; cc++) {
        float4 qv = qs[cc][w];
        float4 kv = ks[cc][kidx];
        a0 += qv.x * kv.x;
        a1 += qv.y * kv.y;
        a2 += qv.z * kv.z;
        a3 += qv.w * kv.w;
    }
    atomicAdd(&g_f[(size_t)n * 9216 + r * 1024 + h * 32 + w],
              (a0 + a1) + (a2 + a3));
}

// ========== Kernel B2: x2 + layernorm rows of f (in place) ==================
__global__ void kB2(const float* __restrict__ g1, const float* __restrict__ be1) {
    int n = blockIdx.x;
    float* f = g_f + (size_t)n * 9216;
    float s = 0.f, q = 0.f;
    for (int j = threadIdx.x; j < 9216; j += 256) {
        float v = 2.f * f[j];
        s += v; q += v * v;
    }
#pragma unroll
    for (int off = 16; off; off >>= 1) {
        s += __shfl_down_sync(0xFFFFFFFFu, s, off);
        q += __shfl_down_sync(0xFFFFFFFFu, q, off);
    }
    __shared__ float sh[34];
    int wv = threadIdx.x >> 5, lane = threadIdx.x & 31;
    if (lane == 0) { sh[wv] = s; sh[wv + 8] = q; }
    __syncthreads();
    if (threadIdx.x == 0) {
        float S = 0.f, Q = 0.f;
        for (int i = 0; i < 8; i++) { S += sh[i]; Q += sh[i + 8]; }
        float mu = S / 9216.f;
        float var = Q / 9216.f - mu * mu;
        sh[32] = mu;
        sh[33] = rsqrtf(var + EPSV);
    }
    __syncthreads();
    float mu = sh[32], rstd = sh[33];
    for (int j = threadIdx.x; j < 9216; j += 256)
        f[j] = (2.f * f[j] - mu) * rstd * g1[j] + be1[j];
}

// ===== Kernel C: split-K tiled GEMM: h1[n,c] partials, 72 K-slices ==========
__global__ void kC(const float* __restrict__ w1) {
    __shared__ float fs[32][33];
    __shared__ float ws[32][65];
    int ct = blockIdx.x, sp = blockIdx.y;
    int t = threadIdx.x;
    int tn = t & 15, tc = t >> 4;
    float acc[2][4];
#pragma unroll
    for (int i = 0; i < 2; i++)
#pragma unroll
        for (int j = 0; j < 4; j++) acc[i][j] = 0.f;

    int j0 = sp * 128;
    for (int k0 = j0; k0 < j0 + 128; k0 += 32) {
        __syncthreads();
#pragma unroll
        for (int i = 0; i < 4; i++) {
            int idx = t + i * 256;
            int n = idx >> 5, kk = idx & 31;
            fs[kk][n] = g_f[(size_t)n * 9216 + k0 + kk];
        }
#pragma unroll
        for (int i = 0; i < 8; i++) {
            int idx = t + i * 256;
            int c = idx >> 5, kk = idx & 31;
            ws[kk][c] = w1[(size_t)(ct * 64 + c) * 9216 + k0 + kk];
        }
        __syncthreads();
#pragma unroll
        for (int kk = 0; kk < 32; kk++) {
            float fv[2], wv[4];
            fv[0] = fs[kk][tn * 2];
            fv[1] = fs[kk][tn * 2 + 1];
#pragma unroll
            for (int j = 0; j < 4; j++) wv[j] = ws[kk][tc * 4 + j];
#pragma unroll
            for (int i = 0; i < 2; i++)
#pragma unroll
                for (int j = 0; j < 4; j++) acc[i][j] += fv[i] * wv[j];
        }
    }
#pragma unroll
    for (int i = 0; i < 2; i++)
#pragma unroll
        for (int j = 0; j < 4; j++)
            g_cpart[(size_t)(sp * 256 + ct * 64 + tc * 4 + j) * 32 + tn * 2 + i] =
                acc[i][j];
}

// -------- Kernel C2: reduce splits, bias, relu, split to fp16 [n][c] --------
__global__ void kC2(const float* __restrict__ b1) {
    int idx = blockIdx.x * 256 + threadIdx.x;  // 8192 = 256c * 32n
    int c = idx >> 5, n = idx & 31;
    float a = b1[c];
#pragma unroll
    for (int sp = 0; sp < 72; sp++) a += g_cpart[(size_t)(sp * 256 + c) * 32 + n];
    a = fmaxf(a, 0.f);
    __half hi = __float2half(a);
    g_h1h[n * 256 + c] = hi;
    g_h1l[n * 256 + c] = __float2half(a - __half2float(hi));
}

// ====== kD_mma: h2 = h1 @ w2^T; fp16 2-term; 4-deep cp.async w2 ring ========
#define WSTR 36
#define BSTR 40
#define KD_WST 0                              // 4 x 128 x WSTR fp32 = 73728 B
#define KD_AH  73728                          // 32 x BSTR fp16 = 2560 B
#define KD_AL  (KD_AH + 2560)
#define KD_BH  (KD_AL + 2560)                 // 128 x BSTR fp16 = 10240 B
#define KD_SM  (KD_BH + 10240)
#define KD_SMEM (KD_SM + 256)
__global__ void __launch_bounds__(256, 2) kD_mma(const float* __restrict__ w2,
                                                 const float* __restrict__ b2) {
    extern __shared__ char dsm[];
    uint32_t sb = smem_u32(dsm);
    float* Wst = (float*)dsm;
    __half* Bh = (__half*)(dsm + KD_BH);
    __half* Ah = (__half*)(dsm + KD_AH);
    __half* Al = (__half*)(dsm + KD_AL);
    float* sm1 = (float*)(dsm + KD_SM);
    float* sm2 = sm1 + 32;

    int t = threadIdx.x, lane = t & 31, wid = t >> 5;
    int bo = blockIdx.x * 128;
    if (t < 32) { sm1[t] = 0.f; sm2[t] = 0.f; }

    float acc[2][2][4];
#pragma unroll
    for (int i = 0; i < 2; i++)
#pragma unroll
        for (int j = 0; j < 2; j++)
#pragma unroll
            for (int kq = 0; kq < 4; kq++) acc[i][j][kq] = 0.f;

    uint32_t sAh = sb + KD_AH, sAl = sb + KD_AL, sBh = sb + KD_BH;

    int a_row = lane & 15;
    int a_koff = (lane >> 4) * 8;
    int b_row = wid * 16 + (lane & 7) + ((lane >> 4) & 1) * 8;
    int b_koff = ((lane >> 3) & 1) * 8;

    auto issueW = [&](int buf, int chunk) {
#pragma unroll
        for (int i = 0; i < 4; i++) {
            int idx = t + i * 256;
            int r = idx >> 3, q = idx & 7;
            cpa16(sb + KD_WST + (uint32_t)(buf * 128 * WSTR + r * WSTR + q * 4) * 4,
                  w2 + (size_t)(bo + r) * 256 + chunk * 32 + q * 4);
        }
        CP_COMMIT();
    };

    issueW(0, 0); issueW(1, 1); issueW(2, 2);
    for (int chunk = 0; chunk < 8; chunk++) {
        int k0 = chunk * 32;
        CP_WAIT2();
        __syncthreads();
        if (chunk + 3 < 8) issueW((chunk + 3) & 3, chunk + 3);
        else CP_COMMIT();                      // keep FIFO group count exact
        // A: 32 rows x 32 fp16 per split
        if (t < 128) {
            int r = t >> 2, q = t & 3;
            *(uint4*)&Ah[r * BSTR + q * 8] = *(const uint4*)&g_h1h[r * 256 + k0 + q * 8];
            *(uint4*)&Al[r * BSTR + q * 8] = *(const uint4*)&g_h1l[r * 256 + k0 + q * 8];
        }
        // convert staged fp32 w2 -> fp16 Bh
        const float* Wb = Wst + (chunk & 3) * 128 * WSTR;
#pragma unroll
        for (int i = 0; i < 4; i++) {
            int idx = t + i * 256;
            int r = idx >> 3, q = idx & 7;
            float4 v = *(const float4*)&Wb[r * WSTR + q * 4];
            __half2 p01 = __floats2half2_rn(v.x, v.y);
            __half2 p23 = __floats2half2_rn(v.z, v.w);
            *(uint2*)&Bh[r * BSTR + q * 4] =
                make_uint2(*(uint32_t*)&p01, *(uint32_t*)&p23);
        }
        __syncthreads();

#pragma unroll
        for (int ks = 0; ks < 2; ks++) {
            uint32_t ah[2][4], al[2][4];
#pragma unroll
            for (int im = 0; im < 2; im++) {
                uint32_t off = ((a_row + im * 16) * BSTR + ks * 16 + a_koff) * 2;
                ldm_x4(ah[im], sAh + off);
                ldm_x4(al[im], sAl + off);
            }
            uint32_t bh[4];
            {
                uint32_t off = (b_row * BSTR + ks * 16 + b_koff) * 2;
                ldm_x4(bh, sBh + off);
            }
#pragma unroll
            for (int im = 0; im < 2; im++)
#pragma unroll
                for (int j = 0; j < 2; j++) {
                    const uint32_t* ph = bh + j * 2;
                    mma_f16(acc[im][j], ah[im], ph);
                    mma_f16(acc[im][j], al[im], ph);
                }
        }
    }

    int g = lane >> 2, t4 = lane & 3;
#pragma unroll
    for (int j = 0; j < 2; j++) {
        int o = bo + wid * 16 + j * 8 + t4 * 2;
        float bb0 = b2[o], bb1 = b2[o + 1];
#pragma unroll
        for (int im = 0; im < 2; im++) {
            int n0 = im * 16 + g, n1 = n0 + 8;
            float v0 = acc[im][j][0] + bb0, v1 = acc[im][j][1] + bb1;
            float v2 = acc[im][j][2] + bb0, v3 = acc[im][j][3] + bb1;
            *(float2*)&g_h2[(size_t)n0 * 131072 + o] = make_float2(v0, v1);
            *(float2*)&g_h2[(size_t)n1 * 131072 + o] = make_float2(v2, v3);
            atomicAdd(&sm1[n0], v0 + v1);
            atomicAdd(&sm2[n0], v0 * v0 + v1 * v1);
            atomicAdd(&sm1[n1], v2 + v3);
            atomicAdd(&sm2[n1], v2 * v2 + v3 * v3);
        }
    }
    __syncthreads();
    if (t < 32) {
        g_dp1[(size_t)blockIdx.x * 32 + t] = sm1[t];
        g_dp2[(size_t)blockIdx.x * 32 + t] = sm2[t];
    }
}

// ---------------- Kernel D2: finish LN stats over 131072/row ----------------
__global__ void kD2() {
    int n = blockIdx.x;
    float s = 0.f, q = 0.f;
    for (int b = threadIdx.x; b < 1024; b += 256) {
        s += g_dp1[(size_t)b * 32 + n];
        q += g_dp2[(size_t)b * 32 + n];
    }
#pragma unroll
    for (int off = 16; off; off >>= 1) {
        s += __shfl_down_sync(0xFFFFFFFFu, s, off);
        q += __shfl_down_sync(0xFFFFFFFFu, q, off);
    }
    __shared__ float sh[16];
    int wv = threadIdx.x >> 5, lane = threadIdx.x & 31;
    if (lane == 0) { sh[wv] = s; sh[wv + 8] = q; }
    __syncthreads();
    if (threadIdx.x == 0) {
        float S = 0.f, Q = 0.f;
        for (int i = 0; i < 8; i++) { S += sh[i]; Q += sh[i + 8]; }
        float mu = S / 131072.f;
        float var = Q / 131072.f - mu * mu;
        g_stats[n * 2] = mu;
        g_stats[n * 2 + 1] = rsqrtf(var + EPSV);
    }
}

// ====== kE0: y = LN(h2) transposed [n][l][c], single fp16 ===================
__global__ void kE0(const float* __restrict__ g2, const float* __restrict__ be2) {
    __shared__ float tile[32][33];
    int c0 = blockIdx.x * 32, l0 = blockIdx.y * 32, n = blockIdx.z;
    int tx = threadIdx.x, ty = threadIdx.y;
    float mu = g_stats[n * 2], rstd = g_stats[n * 2 + 1];
    const float* h2n = g_h2 + (size_t)n * 131072;
#pragma unroll
    for (int k = 0; k < 4; k++) {
        int gidx = (c0 + ty + k * 8) * 1024 + l0 + tx;
        tile[ty + k * 8][tx] = (h2n[gidx] - mu) * rstd * g2[gidx] + be2[gidx];
    }
    __syncthreads();
#pragma unroll
    for (int k = 0; k < 4; k++) {
        int l = l0 + ty + k * 8, c = c0 + tx;
        g_yh[((size_t)n * 1024 + l) * 128 + c] = __float2half(tile[tx][ty + k * 8]);
    }
}

// ====== kE_mma: out = BN(w_out @ y) + x; fp16 2-term; cp.async 3-stage ======
__global__ void __launch_bounds__(256, 2) kE_mma(
    const float* __restrict__ bng, const float* __restrict__ bnb,
    const float* __restrict__ bnm, const float* __restrict__ bnv,
    const float* __restrict__ x, float* __restrict__ out) {
    extern __shared__ char dsm[];
    uint32_t sb = smem_u32(dsm);

    int t = threadIdx.x, lane = t & 31, wid = t >> 5;
    int warp_m = wid & 3, warp_n = wid >> 2;
    int lt = blockIdx.x, ot = blockIdx.y, n = blockIdx.z;

    float acc[2][8][4];
#pragma unroll
    for (int i = 0; i < 2; i++)
#pragma unroll
        for (int j = 0; j < 8; j++)
#pragma unroll
            for (int kq = 0; kq < 4; kq++) acc[i][j][kq] = 0.f;

    int a_row = warp_m * 32 + (lane & 15);
    int a_koff = (lane >> 4) * 8;
    int b_row = warp_n * 64 + (lane & 7) + ((lane >> 4) & 1) * 8;
    int b_koff = ((lane >> 3) & 1) * 8;

    int r = t >> 2, q = t & 3;
    uint32_t so = (uint32_t)(r * ASTR + q * 8) * 2;
    uint32_t so2 = (uint32_t)((r + 64) * ASTR + q * 8) * 2;

    auto issue = [&](int buf, int chunk) {
        uint32_t base = sb + buf * BUF_B;
        int acol = chunk * 32;
        size_t goA = (size_t)(ot * 128 + r) * 128 + acol + q * 8;
        cpa16(base + OFFAH + so, g_voh + goA);
        cpa16(base + OFFAL + so, g_vol + goA);
        cpa16(base + OFFAH + so2, g_voh + goA + 64 * 128);
        cpa16(base + OFFAL + so2, g_vol + goA + 64 * 128);
        size_t goB = ((size_t)n * 1024 + lt * 128 + r) * 128 + acol + q * 8;
        cpa16(base + OFFBH + so, g_yh + goB);
        cpa16(base + OFFBH + so2, g_yh + goB + 64 * 128);
        CP_COMMIT();
    };

    issue(0, 0); issue(1, 1);
    int buf = 0;
    for (int chunk = 0; chunk < 4; chunk++) {
        CP_WAIT1();
        __syncthreads();
        if (chunk + 2 < 4) {
            int nb = buf + 2; if (nb >= 3) nb -= 3;
            issue(nb, chunk + 2);
        } else CP_COMMIT();
        uint32_t base = sb + buf * BUF_B;
        uint32_t sAh = base + OFFAH, sAl = base + OFFAL, sBh = base + OFFBH;

#pragma unroll
        for (int ks = 0; ks < 2; ks++) {
            uint32_t ah[2][4], al[2][4];
#pragma unroll
            for (int im = 0; im < 2; im++) {
                uint32_t off = ((a_row + im * 16) * ASTR + ks * 16 + a_koff) * 2;
                ldm_x4(ah[im], sAh + off);
                ldm_x4(al[im], sAl + off);
            }
            uint32_t bh[4][4];
#pragma unroll
            for (int jn = 0; jn < 4; jn++) {
                uint32_t off = ((b_row + jn * 16) * ASTR + ks * 16 + b_koff) * 2;
                ldm_x4(bh[jn], sBh + off);
            }
#pragma unroll
            for (int im = 0; im < 2; im++)
#pragma unroll
                for (int jb = 0; jb < 8; jb++) {
                    const uint32_t* ph = bh[jb >> 1] + (jb & 1) * 2;
                    mma_f16(acc[im][jb], ah[im], ph);
                    mma_f16(acc[im][jb], al[im], ph);
                }
        }
        if (++buf >= 3) buf = 0;
    }

    int g = lane >> 2, t4 = lane & 3;
#pragma unroll
    for (int im = 0; im < 2; im++) {
        int oa = ot * 128 + warp_m * 32 + im * 16 + g;
        int ob = oa + 8;
        float scA = bng[oa] * rsqrtf(bnv[oa] + EPSV);
        float scB = bng[ob] * rsqrtf(bnv[ob] + EPSV);
        float mbA = bnm[oa], bbA = bnb[oa];
        float mbB = bnm[ob], bbB = bnb[ob];
        const float* xa = x + ((size_t)n * 256 + oa) * 1024;
        const float* xb = x + ((size_t)n * 256 + ob) * 1024;
        float* pa = out + ((size_t)n * 256 + oa) * 1024;
        float* pb = out + ((size_t)n * 256 + ob) * 1024;
#pragma unroll
        for (int jb = 0; jb < 8; jb++) {
            int l = lt * 128 + warp_n * 64 + jb * 8 + t4 * 2;
            float2 xva = *(const float2*)&xa[l];
            float2 xvb = *(const float2*)&xb[l];
            float2 ra, rb;
            ra.x = (acc[im][jb][0] - mbA) * scA + bbA + xva.x;
            ra.y = (acc[im][jb][1] - mbA) * scA + bbA + xva.y;
            rb.x = (acc[im][jb][2] - mbB) * scB + bbB + xvb.x;
            rb.y = (acc[im][jb][3] - mbB) * scB + bbB + xvb.y;
            *(float2*)&pa[l] = ra;
            *(float2*)&pb[l] = rb;
        }
    }
}

// ============================== launcher ====================================
extern "C" void kernel_launch(void* const* d_in, const int* in_sizes, int n_in,
                              void* d_out, int out_size) {
    const float* x    = (const float*)d_in[0];
    const float* wq   = (const float*)d_in[1];
    const float* wk   = (const float*)d_in[2];
    const float* g1   = (const float*)d_in[3];
    const float* be1  = (const float*)d_in[4];
    const float* w1   = (const float*)d_in[5];
    const float* b1   = (const float*)d_in[6];
    const float* w2   = (const float*)d_in[7];
    const float* b2   = (const float*)d_in[8];
    const float* g2   = (const float*)d_in[9];
    const float* be2  = (const float*)d_in[10];
    const float* wout = (const float*)d_in[11];
    const float* bng  = (const float*)d_in[12];
    const float* bnb  = (const float*)d_in[13];
    const float* bnm  = (const float*)d_in[14];
    const float* bnv  = (const float*)d_in[15];
    float* out = (float*)d_out;

    static bool attr_done = false;
    if (!attr_done) {
        cudaFuncSetAttribute(kA2, cudaFuncAttributeMaxDynamicSharedMemorySize,
                             3 * BUF_B);
        cudaFuncSetAttribute(kE_mma, cudaFuncAttributeMaxDynamicSharedMemorySize,
                             3 * BUF_B);
        cudaFuncSetAttribute(kD_mma, cudaFuncAttributeMaxDynamicSharedMemorySize,
                             KD_SMEM);
        attr_done = true;
    }

    kWV<<<384, 256>>>(wq, wk, wout);
    kT<<<dim3(8, 32, 32), dim3(32, 8)>>>(x);
    kA2<<<dim3(8, 2, 32), 256, 3 * BUF_B>>>();
    kB<<<dim3(32, 32, 2), 288>>>();
    kB2<<<32, 256>>>(g1, be1);
    kC<<<dim3(4, 72), 256>>>(w1);
    kC2<<<32, 256>>>(b1);
    kD_mma<<<1024, 256, KD_SMEM>>>(w2, b2);
    kD2<<<32, 256>>>();
    kE0<<<dim3(4, 32, 32), dim3(32, 8)>>>(g2, be2);
    kE_mma<<<dim3(8, 2, 32), 256, 3 * BUF_B>>>(bng, bnb, bnm, bnv, x, out);
}

// round 15
// speedup vs baseline: 1.0767x; 1.0307x over previous
#include <cuda_runtime.h>
#include <cuda_bf16.h>
#include <cuda_fp16.h>
#include <cstdint>

#define EPSV 1e-5f

// ---------------- scratch (device globals; no allocation allowed) ----------
__device__ __align__(16) __half g_qkh[32u * 256u * 1024u]; // [n][o][l] fp16
__device__ float g_f [32u * 9216u];          // [n][r*1024 + l]; kB accumulates
__device__ float g_cpart[72u * 256u * 32u];  // [ksplit][c][n]
__device__ float g_h2[32u * 131072u];        // [n][o]
__device__ float g_dp1[2048u * 32u];
__device__ float g_dp2[2048u * 32u];
__device__ float g_stats[32u * 2u];

// fp16 split operands: A-side hi/lo, B-side single
__device__ __align__(16) __half g_wh[256u * 256u];        // [o][c]
__device__ __align__(16) __half g_wl[256u * 256u];
__device__ __align__(16) __half g_xh[32u * 1024u * 256u]; // [n][l][c]
__device__ __align__(16) __half g_h1h[32u * 256u];        // [n][c]
__device__ __align__(16) __half g_h1l[32u * 256u];
__device__ __align__(16) __half g_yh[32u * 1024u * 128u]; // [n][l][c]
__device__ __align__(16) __half g_voh[256u * 128u];       // [o][c]
__device__ __align__(16) __half g_vol[256u * 128u];

// ======================= warp-MMA helpers ==================================
__device__ __forceinline__ uint32_t smem_u32(const void* p) {
    uint32_t a;
    asm("{ .reg .u64 t; cvta.to.shared.u64 t, %1; cvt.u32.u64 %0, t; }"
        : "=r"(a) : "l"(p));
    return a;
}
__device__ __forceinline__ void ldm_x4(uint32_t* r, uint32_t addr) {
    asm volatile("ldmatrix.sync.aligned.m8n8.x4.shared.b16 {%0,%1,%2,%3}, [%4];"
                 : "=r"(r[0]), "=r"(r[1]), "=r"(r[2]), "=r"(r[3]) : "r"(addr));
}
__device__ __forceinline__ void mma_f16(float* d, const uint32_t* a,
                                        const uint32_t* b) {
    asm volatile(
        "mma.sync.aligned.m16n8k16.row.col.f32.f16.f16.f32 "
        "{%0,%1,%2,%3}, {%4,%5,%6,%7}, {%8,%9}, {%0,%1,%2,%3};"
        : "+f"(d[0]), "+f"(d[1]), "+f"(d[2]), "+f"(d[3])
        : "r"(a[0]), "r"(a[1]), "r"(a[2]), "r"(a[3]), "r"(b[0]), "r"(b[1]));
}
__device__ __forceinline__ void cpa16(uint32_t dst, const void* src) {
    asm volatile("cp.async.cg.shared.global [%0], [%1], 16;"
                 :: "r"(dst), "l"(src));
}
#define CP_COMMIT() asm volatile("cp.async.commit_group;" ::: "memory")
#define CP_WAIT1()  asm volatile("cp.async.wait_group 1;" ::: "memory")
#define CP_WAIT2()  asm volatile("cp.async.wait_group 2;" ::: "memory")

// ==== kWV: split concat(wq,wk)+w_out into fp16 hi/lo; zero g_f ==============
__global__ void kWV(const float* __restrict__ wq, const float* __restrict__ wk,
                    const float* __restrict__ wout) {
    int idx = blockIdx.x * 256 + threadIdx.x;   // 98304 threads
    if (idx < 65536) {
        int o = idx >> 8, c = idx & 255;
        float v = (o < 128) ? wq[o * 256 + c] : wk[(o - 128) * 256 + c];
        __half hi = __float2half(v);
        g_wh[idx] = hi;
        g_wl[idx] = __float2half(v - __half2float(hi));
    } else {
        int j = idx - 65536;
        float v = wout[j];
        __half hi = __float2half(v);
        g_voh[j] = hi;
        g_vol[j] = __float2half(v - __half2float(hi));
    }
    g_f[idx] = 0.f;
    g_f[idx + 98304] = 0.f;
    g_f[idx + 196608] = 0.f;
}

// ====== kT: transpose x[n][c][l] -> xT[n][l][c], single fp16 ================
__global__ void kT(const float* __restrict__ x) {
    __shared__ float tile[32][33];
    int c0 = blockIdx.x * 32, l0 = blockIdx.y * 32, n = blockIdx.z;
    int tx = threadIdx.x, ty = threadIdx.y;
    const float* xn = x + (size_t)n * 256 * 1024;
#pragma unroll
    for (int k = 0; k < 4; k++)
        tile[ty + k * 8][tx] = xn[(size_t)(c0 + ty + k * 8) * 1024 + l0 + tx];
    __syncthreads();
#pragma unroll
    for (int k = 0; k < 4; k++) {
        int l = l0 + ty + k * 8, c = c0 + tx;
        g_xh[((size_t)n * 1024 + l) * 256 + c] = __float2half(tile[tx][ty + k * 8]);
    }
}

// ====== kA2: qk = W @ x, fp16 2-term (Wh+Wl)*xh, cp.async 3-stage ==========
#define ASTR 40
#define TILE_B 10240                        // one 128xASTR fp16 tile bytes
#define BUF_B  (3 * TILE_B)                 // Ah, Al, Bh per stage
#define OFFAH 0
#define OFFAL TILE_B
#define OFFBH (2 * TILE_B)
__global__ void __launch_bounds__(256, 2) kA2() {
    extern __shared__ char dsm[];
    uint32_t sb = smem_u32(dsm);

    int t = threadIdx.x, lane = t & 31, wid = t >> 5;
    int warp_m = wid & 3, warp_n = wid >> 2;
    int lt = blockIdx.x, ot = blockIdx.y, n = blockIdx.z;

    float acc[2][8][4];
#pragma unroll
    for (int i = 0; i < 2; i++)
#pragma unroll
        for (int j = 0; j < 8; j++)
#pragma unroll
            for (int kq = 0; kq < 4; kq++) acc[i][j][kq] = 0.f;

    int a_row = warp_m * 32 + (lane & 15);
    int a_koff = (lane >> 4) * 8;
    int b_row = warp_n * 64 + (lane & 7) + ((lane >> 4) & 1) * 8;
    int b_koff = ((lane >> 3) & 1) * 8;

    int r = t >> 2, q = t & 3;
    uint32_t so = (uint32_t)(r * ASTR + q * 8) * 2;
    uint32_t so2 = (uint32_t)((r + 64) * ASTR + q * 8) * 2;

    auto issue = [&](int buf, int chunk) {
        uint32_t base = sb + buf * BUF_B;
        int acol = chunk * 32;
        size_t goA = (size_t)(ot * 128 + r) * 256 + acol + q * 8;
        cpa16(base + OFFAH + so, g_wh + goA);
        cpa16(base + OFFAL + so, g_wl + goA);
        cpa16(base + OFFAH + so2, g_wh + goA + 64 * 256);
        cpa16(base + OFFAL + so2, g_wl + goA + 64 * 256);
        size_t goB = ((size_t)n * 1024 + lt * 128 + r) * 256 + acol + q * 8;
        cpa16(base + OFFBH + so, g_xh + goB);
        cpa16(base + OFFBH + so2, g_xh + goB + 64 * 256);
        CP_COMMIT();
    };

    issue(0, 0); issue(1, 1);
    int buf = 0;
    for (int chunk = 0; chunk < 8; chunk++) {
        CP_WAIT1();
        __syncthreads();
        if (chunk + 2 < 8) {
            int nb = buf + 2; if (nb >= 3) nb -= 3;
            issue(nb, chunk + 2);
        } else CP_COMMIT();
        uint32_t base = sb + buf * BUF_B;
        uint32_t sAh = base + OFFAH, sAl = base + OFFAL, sBh = base + OFFBH;

#pragma unroll
        for (int ks = 0; ks < 2; ks++) {
            uint32_t ah[2][4], al[2][4];
#pragma unroll
            for (int im = 0; im < 2; im++) {
                uint32_t off = ((a_row + im * 16) * ASTR + ks * 16 + a_koff) * 2;
                ldm_x4(ah[im], sAh + off);
                ldm_x4(al[im], sAl + off);
            }
            uint32_t bh[4][4];
#pragma unroll
            for (int jn = 0; jn < 4; jn++) {
                uint32_t off = ((b_row + jn * 16) * ASTR + ks * 16 + b_koff) * 2;
                ldm_x4(bh[jn], sBh + off);
            }
#pragma unroll
            for (int im = 0; im < 2; im++)
#pragma unroll
                for (int jb = 0; jb < 8; jb++) {
                    const uint32_t* ph = bh[jb >> 1] + (jb & 1) * 2;
                    mma_f16(acc[im][jb], ah[im], ph);
                    mma_f16(acc[im][jb], al[im], ph);
                }
        }
        if (++buf >= 3) buf = 0;
    }

    int g = lane >> 2, t4 = lane & 3;
#pragma unroll
    for (int im = 0; im < 2; im++) {
        int o0 = ot * 128 + warp_m * 32 + im * 16 + g;
#pragma unroll
        for (int jb = 0; jb < 8; jb++) {
            int l = lt * 128 + warp_n * 64 + jb * 8 + t4 * 2;
            __half2 h0 = __floats2half2_rn(acc[im][jb][0], acc[im][jb][1]);
            __half2 h1 = __floats2half2_rn(acc[im][jb][2], acc[im][jb][3]);
            *(__half2*)&g_qkh[((size_t)n * 256 + o0) * 1024 + l] = h0;
            *(__half2*)&g_qkh[((size_t)n * 256 + o0 + 8) * 1024 + l] = h1;
        }
    }
}

// ============ Kernel B: partial f over 64-channel chunk, REDG into g_f ======
// grid (32 h, 32 n, 2 cs); float4-packed channels (c, c+16, c+32, c+48).
// Reads fp16 q/k, converts in loader; inner loop fp32.
__global__ void kB() {
    int h = blockIdx.x, n = blockIdx.y, cs = blockIdx.z;
    __shared__ float4 qs[16][32];    // 8 KB
    __shared__ float4 ks[16][102];   // 25.5 KB
    int t = threadIdx.x;
    int r = t >> 5, w = t & 31;
    int c0 = cs * 64;
    const __half* qn = g_qkh + (size_t)n * 256 * 1024;
    const __half* kn = qn + 128u * 1024u;
    int hh = r / 3, dw = r % 3;
    int kidx = hh * 34 + w + dw;

    for (int idx = t; idx < 16 * 32; idx += 288) {
        int cc = idx >> 5, ww = idx & 31;
        const __half* b = qn + (size_t)(c0 + cc) * 1024 + h * 32 + ww;
        qs[cc][ww] = make_float4(__half2float(b[0]),
                                 __half2float(b[16 * 1024]),
                                 __half2float(b[32 * 1024]),
                                 __half2float(b[48 * 1024]));
    }
    for (int idx = t; idx < 16 * 102; idx += 288) {
        int cc = idx / 102, rem = idx % 102;
        int rr = rem / 34, ww = rem % 34;
        int hg = h + rr - 1, wg = ww - 1;
        float4 v = make_float4(0.f, 0.f, 0.f, 0.f);
        if (hg >= 0 && hg < 32 && wg >= 0 && wg < 32) {
            const __half* b = kn + (size_t)(c0 + cc) * 1024 + hg * 32 + wg;
            v = make_float4(__half2float(b[0]),
                            __half2float(b[16 * 1024]),
                            __half2float(b[32 * 1024]),
                            __half2float(b[48 * 1024]));
        }
        ks[cc][rem] = v;
    }
    __syncthreads();
    float a0 = 0.f, a1 = 0.f, a2 = 0.f, a3 = 0.f;
#pragma unroll
    for (int cc = 0; cc < 16; cc++) {
        float4 qv = qs[cc][w];
        float4 kv = ks[cc][kidx];
        a0 += qv.x * kv.x;
        a1 += qv.y * kv.y;
        a2 += qv.z * kv.z;
        a3 += qv.w * kv.w;
    }
    atomicAdd(&g_f[(size_t)n * 9216 + r * 1024 + h * 32 + w],
              (a0 + a1) + (a2 + a3));
}

// ========== Kernel B2: x2 + layernorm rows of f (in place) ==================
__global__ void kB2(const float* __restrict__ g1, const float* __restrict__ be1) {
    int n = blockIdx.x;
    float* f = g_f + (size_t)n * 9216;
    float s = 0.f, q = 0.f;
    for (int j = threadIdx.x; j < 9216; j += 256) {
        float v = 2.f * f[j];
        s += v; q += v * v;
    }
#pragma unroll
    for (int off = 16; off; off >>= 1) {
        s += __shfl_down_sync(0xFFFFFFFFu, s, off);
        q += __shfl_down_sync(0xFFFFFFFFu, q, off);
    }
    __shared__ float sh[34];
    int wv = threadIdx.x >> 5, lane = threadIdx.x & 31;
    if (lane == 0) { sh[wv] = s; sh[wv + 8] = q; }
    __syncthreads();
    if (threadIdx.x == 0) {
        float S = 0.f, Q = 0.f;
        for (int i = 0; i < 8; i++) { S += sh[i]; Q += sh[i + 8]; }
        float mu = S / 9216.f;
        float var = Q / 9216.f - mu * mu;
        sh[32] = mu;
        sh[33] = rsqrtf(var + EPSV);
    }
    __syncthreads();
    float mu = sh[32], rstd = sh[33];
    for (int j = threadIdx.x; j < 9216; j += 256)
        f[j] = (2.f * f[j] - mu) * rstd * g1[j] + be1[j];
}

// ===== Kernel C: split-K tiled GEMM: h1[n,c] partials, 72 K-slices ==========
__global__ void kC(const float* __restrict__ w1) {
    __shared__ float fs[32][33];
    __shared__ float ws[32][65];
    int ct = blockIdx.x, sp = blockIdx.y;
    int t = threadIdx.x;
    int tn = t & 15, tc = t >> 4;
    float acc[2][4];
#pragma unroll
    for (int i = 0; i < 2; i++)
#pragma unroll
        for (int j = 0; j < 4; j++) acc[i][j] = 0.f;

    int j0 = sp * 128;
    for (int k0 = j0; k0 < j0 + 128; k0 += 32) {
        __syncthreads();
#pragma unroll
        for (int i = 0; i < 4; i++) {
            int idx = t + i * 256;
            int n = idx >> 5, kk = idx & 31;
            fs[kk][n] = g_f[(size_t)n * 9216 + k0 + kk];
        }
#pragma unroll
        for (int i = 0; i < 8; i++) {
            int idx = t + i * 256;
            int c = idx >> 5, kk = idx & 31;
            ws[kk][c] = w1[(size_t)(ct * 64 + c) * 9216 + k0 + kk];
        }
        __syncthreads();
#pragma unroll
        for (int kk = 0; kk < 32; kk++) {
            float fv[2], wv[4];
            fv[0] = fs[kk][tn * 2];
            fv[1] = fs[kk][tn * 2 + 1];
#pragma unroll
            for (int j = 0; j < 4; j++) wv[j] = ws[kk][tc * 4 + j];
#pragma unroll
            for (int i = 0; i < 2; i++)
#pragma unroll
                for (int j = 0; j < 4; j++) acc[i][j] += fv[i] * wv[j];
        }
    }
#pragma unroll
    for (int i = 0; i < 2; i++)
#pragma unroll
        for (int j = 0; j < 4; j++)
            g_cpart[(size_t)(sp * 256 + ct * 64 + tc * 4 + j) * 32 + tn * 2 + i] =
                acc[i][j];
}

// -------- Kernel C2: reduce splits, bias, relu, split to fp16 [n][c] --------
__global__ void kC2(const float* __restrict__ b1) {
    int idx = blockIdx.x * 256 + threadIdx.x;  // 8192 = 256c * 32n
    int c = idx >> 5, n = idx & 31;
    float a = b1[c];
#pragma unroll
    for (int sp = 0; sp < 72; sp++) a += g_cpart[(size_t)(sp * 256 + c) * 32 + n];
    a = fmaxf(a, 0.f);
    __half hi = __float2half(a);
    g_h1h[n * 256 + c] = hi;
    g_h1l[n * 256 + c] = __float2half(a - __half2float(hi));
}

// ====== kD_mma: h2 = h1 @ w2^T; fp16 2-term; 4-deep cp.async w2 ring ========
#define WSTR 36
#define BSTR 40
#define KD_WST 0                              // 4 x 128 x WSTR fp32 = 73728 B
#define KD_AH  73728                          // 32 x BSTR fp16 = 2560 B
#define KD_AL  (KD_AH + 2560)
#define KD_BH  (KD_AL + 2560)                 // 128 x BSTR fp16 = 10240 B
#define KD_SM  (KD_BH + 10240)
#define KD_SMEM (KD_SM + 256)
__global__ void __launch_bounds__(256, 2) kD_mma(const float* __restrict__ w2,
                                                 const float* __restrict__ b2) {
    extern __shared__ char dsm[];
    uint32_t sb = smem_u32(dsm);
    float* Wst = (float*)dsm;
    __half* Bh = (__half*)(dsm + KD_BH);
    __half* Ah = (__half*)(dsm + KD_AH);
    __half* Al = (__half*)(dsm + KD_AL);
    float* sm1 = (float*)(dsm + KD_SM);
    float* sm2 = sm1 + 32;

    int t = threadIdx.x, lane = t & 31, wid = t >> 5;
    int bo = blockIdx.x * 128;
    if (t < 32) { sm1[t] = 0.f; sm2[t] = 0.f; }

    float acc[2][2][4];
#pragma unroll
    for (int i = 0; i < 2; i++)
#pragma unroll
        for (int j = 0; j < 2; j++)
#pragma unroll
            for (int kq = 0; kq < 4; kq++) acc[i][j][kq] = 0.f;

    uint32_t sAh = sb + KD_AH, sAl = sb + KD_AL, sBh = sb + KD_BH;

    int a_row = lane & 15;
    int a_koff = (lane >> 4) * 8;
    int b_row = wid * 16 + (lane & 7) + ((lane >> 4) & 1) * 8;
    int b_koff = ((lane >> 3) & 1) * 8;

    auto issueW = [&](int buf, int chunk) {
#pragma unroll
        for (int i = 0; i < 4; i++) {
            int idx = t + i * 256;
            int r = idx >> 3, q = idx & 7;
            cpa16(sb + KD_WST + (uint32_t)(buf * 128 * WSTR + r * WSTR + q * 4) * 4,
                  w2 + (size_t)(bo + r) * 256 + chunk * 32 + q * 4);
        }
        CP_COMMIT();
    };

    issueW(0, 0); issueW(1, 1); issueW(2, 2);
    for (int chunk = 0; chunk < 8; chunk++) {
        int k0 = chunk * 32;
        CP_WAIT2();
        __syncthreads();
        if (chunk + 3 < 8) issueW((chunk + 3) & 3, chunk + 3);
        else CP_COMMIT();                      // keep FIFO group count exact
        // A: 32 rows x 32 fp16 per split
        if (t < 128) {
            int r = t >> 2, q = t & 3;
            *(uint4*)&Ah[r * BSTR + q * 8] = *(const uint4*)&g_h1h[r * 256 + k0 + q * 8];
            *(uint4*)&Al[r * BSTR + q * 8] = *(const uint4*)&g_h1l[r * 256 + k0 + q * 8];
        }
        // convert staged fp32 w2 -> fp16 Bh
        const float* Wb = Wst + (chunk & 3) * 128 * WSTR;
#pragma unroll
        for (int i = 0; i < 4; i++) {
            int idx = t + i * 256;
            int r = idx >> 3, q = idx & 7;
            float4 v = *(const float4*)&Wb[r * WSTR + q * 4];
            __half2 p01 = __floats2half2_rn(v.x, v.y);
            __half2 p23 = __floats2half2_rn(v.z, v.w);
            *(uint2*)&Bh[r * BSTR + q * 4] =
                make_uint2(*(uint32_t*)&p01, *(uint32_t*)&p23);
        }
        __syncthreads();

#pragma unroll
        for (int ks = 0; ks < 2; ks++) {
            uint32_t ah[2][4], al[2][4];
#pragma unroll
            for (int im = 0; im < 2; im++) {
                uint32_t off = ((a_row + im * 16) * BSTR + ks * 16 + a_koff) * 2;
                ldm_x4(ah[im], sAh + off);
                ldm_x4(al[im], sAl + off);
            }
            uint32_t bh[4];
            {
                uint32_t off = (b_row * BSTR + ks * 16 + b_koff) * 2;
                ldm_x4(bh, sBh + off);
            }
#pragma unroll
            for (int im = 0; im < 2; im++)
#pragma unroll
                for (int j = 0; j < 2; j++) {
                    const uint32_t* ph = bh + j * 2;
                    mma_f16(acc[im][j], ah[im], ph);
                    mma_f16(acc[im][j], al[im], ph);
                }
        }
    }

    int g = lane >> 2, t4 = lane & 3;
#pragma unroll
    for (int j = 0; j < 2; j++) {
        int o = bo + wid * 16 + j * 8 + t4 * 2;
        float bb0 = b2[o], bb1 = b2[o + 1];
#pragma unroll
        for (int im = 0; im < 2; im++) {
            int n0 = im * 16 + g, n1 = n0 + 8;
            float v0 = acc[im][j][0] + bb0, v1 = acc[im][j][1] + bb1;
            float v2 = acc[im][j][2] + bb0, v3 = acc[im][j][3] + bb1;
            *(float2*)&g_h2[(size_t)n0 * 131072 + o] = make_float2(v0, v1);
            *(float2*)&g_h2[(size_t)n1 * 131072 + o] = make_float2(v2, v3);
            atomicAdd(&sm1[n0], v0 + v1);
            atomicAdd(&sm2[n0], v0 * v0 + v1 * v1);
            atomicAdd(&sm1[n1], v2 + v3);
            atomicAdd(&sm2[n1], v2 * v2 + v3 * v3);
        }
    }
    __syncthreads();
    if (t < 32) {
        g_dp1[(size_t)blockIdx.x * 32 + t] = sm1[t];
        g_dp2[(size_t)blockIdx.x * 32 + t] = sm2[t];
    }
}

// ---------------- Kernel D2: finish LN stats over 131072/row ----------------
__global__ void kD2() {
    int n = blockIdx.x;
    float s = 0.f, q = 0.f;
    for (int b = threadIdx.x; b < 1024; b += 256) {
        s += g_dp1[(size_t)b * 32 + n];
        q += g_dp2[(size_t)b * 32 + n];
    }
#pragma unroll
    for (int off = 16; off; off >>= 1) {
        s += __shfl_down_sync(0xFFFFFFFFu, s, off);
        q += __shfl_down_sync(0xFFFFFFFFu, q, off);
    }
    __shared__ float sh[16];
    int wv = threadIdx.x >> 5, lane = threadIdx.x & 31;
    if (lane == 0) { sh[wv] = s; sh[wv + 8] = q; }
    __syncthreads();
    if (threadIdx.x == 0) {
        float S = 0.f, Q = 0.f;
        for (int i = 0; i < 8; i++) { S += sh[i]; Q += sh[i + 8]; }
        float mu = S / 131072.f;
        float var = Q / 131072.f - mu * mu;
        g_stats[n * 2] = mu;
        g_stats[n * 2 + 1] = rsqrtf(var + EPSV);
    }
}

// ====== kE0: y = LN(h2) transposed [n][l][c], single fp16 ===================
__global__ void kE0(const float* __restrict__ g2, const float* __restrict__ be2) {
    __shared__ float tile[32][33];
    int c0 = blockIdx.x * 32, l0 = blockIdx.y * 32, n = blockIdx.z;
    int tx = threadIdx.x, ty = threadIdx.y;
    float mu = g_stats[n * 2], rstd = g_stats[n * 2 + 1];
    const float* h2n = g_h2 + (size_t)n * 131072;
#pragma unroll
    for (int k = 0; k < 4; k++) {
        int gidx = (c0 + ty + k * 8) * 1024 + l0 + tx;
        tile[ty + k * 8][tx] = (h2n[gidx] - mu) * rstd * g2[gidx] + be2[gidx];
    }
    __syncthreads();
#pragma unroll
    for (int k = 0; k < 4; k++) {
        int l = l0 + ty + k * 8, c = c0 + tx;
        g_yh[((size_t)n * 1024 + l) * 128 + c] = __float2half(tile[tx][ty + k * 8]);
    }
}

// ====== kE_mma: out = BN(w_out @ y) + x; fp16 2-term; cp.async 3-stage ======
__global__ void __launch_bounds__(256, 2) kE_mma(
    const float* __restrict__ bng, const float* __restrict__ bnb,
    const float* __restrict__ bnm, const float* __restrict__ bnv,
    const float* __restrict__ x, float* __restrict__ out) {
    extern __shared__ char dsm[];
    uint32_t sb = smem_u32(dsm);

    int t = threadIdx.x, lane = t & 31, wid = t >> 5;
    int warp_m = wid & 3, warp_n = wid >> 2;
    int lt = blockIdx.x, ot = blockIdx.y, n = blockIdx.z;

    float acc[2][8][4];
#pragma unroll
    for (int i = 0; i < 2; i++)
#pragma unroll
        for (int j = 0; j < 8; j++)
#pragma unroll
            for (int kq = 0; kq < 4; kq++) acc[i][j][kq] = 0.f;

    int a_row = warp_m * 32 + (lane & 15);
    int a_koff = (lane >> 4) * 8;
    int b_row = warp_n * 64 + (lane & 7) + ((lane >> 4) & 1) * 8;
    int b_koff = ((lane >> 3) & 1) * 8;

    int r = t >> 2, q = t & 3;
    uint32_t so = (uint32_t)(r * ASTR + q * 8) * 2;
    uint32_t so2 = (uint32_t)((r + 64) * ASTR + q * 8) * 2;

    auto issue = [&](int buf, int chunk) {
        uint32_t base = sb + buf * BUF_B;
        int acol = chunk * 32;
        size_t goA = (size_t)(ot * 128 + r) * 128 + acol + q * 8;
        cpa16(base + OFFAH + so, g_voh + goA);
        cpa16(base + OFFAL + so, g_vol + goA);
        cpa16(base + OFFAH + so2, g_voh + goA + 64 * 128);
        cpa16(base + OFFAL + so2, g_vol + goA + 64 * 128);
        size_t goB = ((size_t)n * 1024 + lt * 128 + r) * 128 + acol + q * 8;
        cpa16(base + OFFBH + so, g_yh + goB);
        cpa16(base + OFFBH + so2, g_yh + goB + 64 * 128);
        CP_COMMIT();
    };

    issue(0, 0); issue(1, 1);
    int buf = 0;
    for (int chunk = 0; chunk < 4; chunk++) {
        CP_WAIT1();
        __syncthreads();
        if (chunk + 2 < 4) {
            int nb = buf + 2; if (nb >= 3) nb -= 3;
            issue(nb, chunk + 2);
        } else CP_COMMIT();
        uint32_t base = sb + buf * BUF_B;
        uint32_t sAh = base + OFFAH, sAl = base + OFFAL, sBh = base + OFFBH;

#pragma unroll
        for (int ks = 0; ks < 2; ks++) {
            uint32_t ah[2][4], al[2][4];
#pragma unroll
            for (int im = 0; im < 2; im++) {
                uint32_t off = ((a_row + im * 16) * ASTR + ks * 16 + a_koff) * 2;
                ldm_x4(ah[im], sAh + off);
                ldm_x4(al[im], sAl + off);
            }
            uint32_t bh[4][4];
#pragma unroll
            for (int jn = 0; jn < 4; jn++) {
                uint32_t off = ((b_row + jn * 16) * ASTR + ks * 16 + b_koff) * 2;
                ldm_x4(bh[jn], sBh + off);
            }
#pragma unroll
            for (int im = 0; im < 2; im++)
#pragma unroll
                for (int jb = 0; jb < 8; jb++) {
                    const uint32_t* ph = bh[jb >> 1] + (jb & 1) * 2;
                    mma_f16(acc[im][jb], ah[im], ph);
                    mma_f16(acc[im][jb], al[im], ph);
                }
        }
        if (++buf >= 3) buf = 0;
    }

    int g = lane >> 2, t4 = lane & 3;
#pragma unroll
    for (int im = 0; im < 2; im++) {
        int oa = ot * 128 + warp_m * 32 + im * 16 + g;
        int ob = oa + 8;
        float scA = bng[oa] * rsqrtf(bnv[oa] + EPSV);
        float scB = bng[ob] * rsqrtf(bnv[ob] + EPSV);
        float mbA = bnm[oa], bbA = bnb[oa];
        float mbB = bnm[ob], bbB = bnb[ob];
        const float* xa = x + ((size_t)n * 256 + oa) * 1024;
        const float* xb = x + ((size_t)n * 256 + ob) * 1024;
        float* pa = out + ((size_t)n * 256 + oa) * 1024;
        float* pb = out + ((size_t)n * 256 + ob) * 1024;
#pragma unroll
        for (int jb = 0; jb < 8; jb++) {
            int l = lt * 128 + warp_n * 64 + jb * 8 + t4 * 2;
            float2 xva = *(const float2*)&xa[l];
            float2 xvb = *(const float2*)&xb[l];
            float2 ra, rb;
            ra.x = (acc[im][jb][0] - mbA) * scA + bbA + xva.x;
            ra.y = (acc[im][jb][1] - mbA) * scA + bbA + xva.y;
            rb.x = (acc[im][jb][2] - mbB) * scB + bbB + xvb.x;
            rb.y = (acc[im][jb][3] - mbB) * scB + bbB + xvb.y;
            *(float2*)&pa[l] = ra;
            *(float2*)&pb[l] = rb;
        }
    }
}

// ============================== launcher ====================================
extern "C" void kernel_launch(void* const* d_in, const int* in_sizes, int n_in,
                              void* d_out, int out_size) {
    const float* x    = (const float*)d_in[0];
    const float* wq   = (const float*)d_in[1];
    const float* wk   = (const float*)d_in[2];
    const float* g1   = (const float*)d_in[3];
    const float* be1  = (const float*)d_in[4];
    const float* w1   = (const float*)d_in[5];
    const float* b1   = (const float*)d_in[6];
    const float* w2   = (const float*)d_in[7];
    const float* b2   = (const float*)d_in[8];
    const float* g2   = (const float*)d_in[9];
    const float* be2  = (const float*)d_in[10];
    const float* wout = (const float*)d_in[11];
    const float* bng  = (const float*)d_in[12];
    const float* bnb  = (const float*)d_in[13];
    const float* bnm  = (const float*)d_in[14];
    const float* bnv  = (const float*)d_in[15];
    float* out = (float*)d_out;

    static bool attr_done = false;
    if (!attr_done) {
        cudaFuncSetAttribute(kA2, cudaFuncAttributeMaxDynamicSharedMemorySize,
                             3 * BUF_B);
        cudaFuncSetAttribute(kE_mma, cudaFuncAttributeMaxDynamicSharedMemorySize,
                             3 * BUF_B);
        cudaFuncSetAttribute(kD_mma, cudaFuncAttributeMaxDynamicSharedMemorySize,
                             KD_SMEM);
        attr_done = true;
    }

    kWV<<<384, 256>>>(wq, wk, wout);
    kT<<<dim3(8, 32, 32), dim3(32, 8)>>>(x);
    kA2<<<dim3(8, 2, 32), 256, 3 * BUF_B>>>();
    kB<<<dim3(32, 32, 2), 288>>>();
    kB2<<<32, 256>>>(g1, be1);
    kC<<<dim3(4, 72), 256>>>(w1);
    kC2<<<32, 256>>>(b1);
    kD_mma<<<1024, 256, KD_SMEM>>>(w2, b2);
    kD2<<<32, 256>>>();
    kE0<<<dim3(4, 32, 32), dim3(32, 8)>>>(g2, be2);
    kE_mma<<<dim3(8, 2, 32), 256, 3 * BUF_B>>>(bng, bnb, bnm, bnv, x, out);
}

// round 16
// speedup vs baseline: 1.1630x; 1.0802x over previous
#include <cuda_runtime.h>
#include <cuda_bf16.h>
#include <cuda_fp16.h>
#include <cstdint>

#define EPSV 1e-5f

// ---------------- scratch (device globals; no allocation allowed) ----------
__device__ __align__(16) __half g_qkh[32u * 256u * 1024u]; // [n][o][l] fp16
__device__ float g_f [32u * 9216u];          // [n][r*1024 + l]; kB accumulates
__device__ float g_cpart[72u * 256u * 32u];  // [ksplit][c][n]
__device__ float g_h2[32u * 131072u];        // [n][o]
__device__ float g_dp1[2048u * 32u];
__device__ float g_dp2[2048u * 32u];
__device__ float g_stats[32u * 2u];

// fp16 operands
__device__ __align__(16) __half g_wh[256u * 256u];        // [o][c]
__device__ __align__(16) __half g_xh[32u * 1024u * 256u]; // [n][l][c]
__device__ __align__(16) __half g_h1h[32u * 256u];        // [n][c]
__device__ __align__(16) __half g_h1l[32u * 256u];
__device__ __align__(16) __half g_yh[32u * 1024u * 128u]; // [n][l][c]
__device__ __align__(16) __half g_voh[256u * 128u];       // [o][c]

// ======================= warp-MMA helpers ==================================
__device__ __forceinline__ uint32_t smem_u32(const void* p) {
    uint32_t a;
    asm("{ .reg .u64 t; cvta.to.shared.u64 t, %1; cvt.u32.u64 %0, t; }"
        : "=r"(a) : "l"(p));
    return a;
}
__device__ __forceinline__ void ldm_x4(uint32_t* r, uint32_t addr) {
    asm volatile("ldmatrix.sync.aligned.m8n8.x4.shared.b16 {%0,%1,%2,%3}, [%4];"
                 : "=r"(r[0]), "=r"(r[1]), "=r"(r[2]), "=r"(r[3]) : "r"(addr));
}
__device__ __forceinline__ void mma_f16(float* d, const uint32_t* a,
                                        const uint32_t* b) {
    asm volatile(
        "mma.sync.aligned.m16n8k16.row.col.f32.f16.f16.f32 "
        "{%0,%1,%2,%3}, {%4,%5,%6,%7}, {%8,%9}, {%0,%1,%2,%3};"
        : "+f"(d[0]), "+f"(d[1]), "+f"(d[2]), "+f"(d[3])
        : "r"(a[0]), "r"(a[1]), "r"(a[2]), "r"(a[3]), "r"(b[0]), "r"(b[1]));
}
__device__ __forceinline__ void cpa16(uint32_t dst, const void* src) {
    asm volatile("cp.async.cg.shared.global [%0], [%1], 16;"
                 :: "r"(dst), "l"(src));
}
#define CP_COMMIT() asm volatile("cp.async.commit_group;" ::: "memory")
#define CP_WAIT1()  asm volatile("cp.async.wait_group 1;" ::: "memory")
#define CP_WAIT2()  asm volatile("cp.async.wait_group 2;" ::: "memory")

// ==== kWV: convert concat(wq,wk)+w_out to fp16; zero g_f ====================
__global__ void kWV(const float* __restrict__ wq, const float* __restrict__ wk,
                    const float* __restrict__ wout) {
    int idx = blockIdx.x * 256 + threadIdx.x;   // 98304 threads
    if (idx < 65536) {
        int o = idx >> 8, c = idx & 255;
        float v = (o < 128) ? wq[o * 256 + c] : wk[(o - 128) * 256 + c];
        g_wh[idx] = __float2half(v);
    } else {
        int j = idx - 65536;
        g_voh[j] = __float2half(wout[j]);
    }
    g_f[idx] = 0.f;
    g_f[idx + 98304] = 0.f;
    g_f[idx + 196608] = 0.f;
}

// ====== kT: transpose x[n][c][l] -> xT[n][l][c], single fp16 ================
__global__ void kT(const float* __restrict__ x) {
    __shared__ float tile[32][33];
    int c0 = blockIdx.x * 32, l0 = blockIdx.y * 32, n = blockIdx.z;
    int tx = threadIdx.x, ty = threadIdx.y;
    const float* xn = x + (size_t)n * 256 * 1024;
#pragma unroll
    for (int k = 0; k < 4; k++)
        tile[ty + k * 8][tx] = xn[(size_t)(c0 + ty + k * 8) * 1024 + l0 + tx];
    __syncthreads();
#pragma unroll
    for (int k = 0; k < 4; k++) {
        int l = l0 + ty + k * 8, c = c0 + tx;
        g_xh[((size_t)n * 1024 + l) * 256 + c] = __float2half(tile[tx][ty + k * 8]);
    }
}

// ====== kA2: qk = W @ x, pure fp16, cp.async 3-stage ========================
#define ASTR 40
#define TILE_B 10240                        // one 128xASTR fp16 tile bytes
#define BUF_B  (2 * TILE_B)                 // Ah, Bh per stage
#define OFFAH 0
#define OFFBH TILE_B
__global__ void __launch_bounds__(256, 2) kA2() {
    extern __shared__ char dsm[];
    uint32_t sb = smem_u32(dsm);

    int t = threadIdx.x, lane = t & 31, wid = t >> 5;
    int warp_m = wid & 3, warp_n = wid >> 2;
    int lt = blockIdx.x, ot = blockIdx.y, n = blockIdx.z;

    float acc[2][8][4];
#pragma unroll
    for (int i = 0; i < 2; i++)
#pragma unroll
        for (int j = 0; j < 8; j++)
#pragma unroll
            for (int kq = 0; kq < 4; kq++) acc[i][j][kq] = 0.f;

    int a_row = warp_m * 32 + (lane & 15);
    int a_koff = (lane >> 4) * 8;
    int b_row = warp_n * 64 + (lane & 7) + ((lane >> 4) & 1) * 8;
    int b_koff = ((lane >> 3) & 1) * 8;

    int r = t >> 2, q = t & 3;
    uint32_t so = (uint32_t)(r * ASTR + q * 8) * 2;
    uint32_t so2 = (uint32_t)((r + 64) * ASTR + q * 8) * 2;

    auto issue = [&](int buf, int chunk) {
        uint32_t base = sb + buf * BUF_B;
        int acol = chunk * 32;
        size_t goA = (size_t)(ot * 128 + r) * 256 + acol + q * 8;
        cpa16(base + OFFAH + so, g_wh + goA);
        cpa16(base + OFFAH + so2, g_wh + goA + 64 * 256);
        size_t goB = ((size_t)n * 1024 + lt * 128 + r) * 256 + acol + q * 8;
        cpa16(base + OFFBH + so, g_xh + goB);
        cpa16(base + OFFBH + so2, g_xh + goB + 64 * 256);
        CP_COMMIT();
    };

    issue(0, 0); issue(1, 1);
    int buf = 0;
    for (int chunk = 0; chunk < 8; chunk++) {
        CP_WAIT1();
        __syncthreads();
        if (chunk + 2 < 8) {
            int nb = buf + 2; if (nb >= 3) nb -= 3;
            issue(nb, chunk + 2);
        } else CP_COMMIT();
        uint32_t base = sb + buf * BUF_B;
        uint32_t sAh = base + OFFAH, sBh = base + OFFBH;

#pragma unroll
        for (int ks = 0; ks < 2; ks++) {
            uint32_t ah[2][4];
#pragma unroll
            for (int im = 0; im < 2; im++) {
                uint32_t off = ((a_row + im * 16) * ASTR + ks * 16 + a_koff) * 2;
                ldm_x4(ah[im], sAh + off);
            }
            uint32_t bh[4][4];
#pragma unroll
            for (int jn = 0; jn < 4; jn++) {
                uint32_t off = ((b_row + jn * 16) * ASTR + ks * 16 + b_koff) * 2;
                ldm_x4(bh[jn], sBh + off);
            }
#pragma unroll
            for (int im = 0; im < 2; im++)
#pragma unroll
                for (int jb = 0; jb < 8; jb++) {
                    const uint32_t* ph = bh[jb >> 1] + (jb & 1) * 2;
                    mma_f16(acc[im][jb], ah[im], ph);
                }
        }
        if (++buf >= 3) buf = 0;
    }

    int g = lane >> 2, t4 = lane & 3;
#pragma unroll
    for (int im = 0; im < 2; im++) {
        int o0 = ot * 128 + warp_m * 32 + im * 16 + g;
#pragma unroll
        for (int jb = 0; jb < 8; jb++) {
            int l = lt * 128 + warp_n * 64 + jb * 8 + t4 * 2;
            __half2 h0 = __floats2half2_rn(acc[im][jb][0], acc[im][jb][1]);
            __half2 h1 = __floats2half2_rn(acc[im][jb][2], acc[im][jb][3]);
            *(__half2*)&g_qkh[((size_t)n * 256 + o0) * 1024 + l] = h0;
            *(__half2*)&g_qkh[((size_t)n * 256 + o0 + 8) * 1024 + l] = h1;
        }
    }
}

// ============ Kernel B: partial f over 64-channel chunk, REDG into g_f ======
__global__ void kB() {
    int h = blockIdx.x, n = blockIdx.y, cs = blockIdx.z;
    __shared__ float4 qs[16][32];    // 8 KB
    __shared__ float4 ks[16][102];   // 25.5 KB
    int t = threadIdx.x;
    int r = t >> 5, w = t & 31;
    int c0 = cs * 64;
    const __half* qn = g_qkh + (size_t)n * 256 * 1024;
    const __half* kn = qn + 128u * 1024u;
    int hh = r / 3, dw = r % 3;
    int kidx = hh * 34 + w + dw;

    for (int idx = t; idx < 16 * 32; idx += 288) {
        int cc = idx >> 5, ww = idx & 31;
        const __half* b = qn + (size_t)(c0 + cc) * 1024 + h * 32 + ww;
        qs[cc][ww] = make_float4(__half2float(b[0]),
                                 __half2float(b[16 * 1024]),
                                 __half2float(b[32 * 1024]),
                                 __half2float(b[48 * 1024]));
    }
    for (int idx = t; idx < 16 * 102; idx += 288) {
        int cc = idx / 102, rem = idx % 102;
        int rr = rem / 34, ww = rem % 34;
        int hg = h + rr - 1, wg = ww - 1;
        float4 v = make_float4(0.f, 0.f, 0.f, 0.f);
        if (hg >= 0 && hg < 32 && wg >= 0 && wg < 32) {
            const __half* b = kn + (size_t)(c0 + cc) * 1024 + hg * 32 + wg;
            v = make_float4(__half2float(b[0]),
                            __half2float(b[16 * 1024]),
                            __half2float(b[32 * 1024]),
                            __half2float(b[48 * 1024]));
        }
        ks[cc][rem] = v;
    }
    __syncthreads();
    float a0 = 0.f, a1 = 0.f, a2 = 0.f, a3 = 0.f;
#pragma unroll
    for (int cc = 0; cc < 16; cc++) {
        float4 qv = qs[cc][w];
        float4 kv = ks[cc][kidx];
        a0 += qv.x * kv.x;
        a1 += qv.y * kv.y;
        a2 += qv.z * kv.z;
        a3 += qv.w * kv.w;
    }
    atomicAdd(&g_f[(size_t)n * 9216 + r * 1024 + h * 32 + w],
              (a0 + a1) + (a2 + a3));
}

// ========== Kernel B2: x2 + layernorm rows of f (in place) ==================
__global__ void kB2(const float* __restrict__ g1, const float* __restrict__ be1) {
    int n = blockIdx.x;
    float* f = g_f + (size_t)n * 9216;
    float s = 0.f, q = 0.f;
    for (int j = threadIdx.x; j < 9216; j += 256) {
        float v = 2.f * f[j];
        s += v; q += v * v;
    }
#pragma unroll
    for (int off = 16; off; off >>= 1) {
        s += __shfl_down_sync(0xFFFFFFFFu, s, off);
        q += __shfl_down_sync(0xFFFFFFFFu, q, off);
    }
    __shared__ float sh[34];
    int wv = threadIdx.x >> 5, lane = threadIdx.x & 31;
    if (lane == 0) { sh[wv] = s; sh[wv + 8] = q; }
    __syncthreads();
    if (threadIdx.x == 0) {
        float S = 0.f, Q = 0.f;
        for (int i = 0; i < 8; i++) { S += sh[i]; Q += sh[i + 8]; }
        float mu = S / 9216.f;
        float var = Q / 9216.f - mu * mu;
        sh[32] = mu;
        sh[33] = rsqrtf(var + EPSV);
    }
    __syncthreads();
    float mu = sh[32], rstd = sh[33];
    for (int j = threadIdx.x; j < 9216; j += 256)
        f[j] = (2.f * f[j] - mu) * rstd * g1[j] + be1[j];
}

// ===== Kernel C: split-K tiled GEMM: h1[n,c] partials, 72 K-slices ==========
__global__ void kC(const float* __restrict__ w1) {
    __shared__ float fs[32][33];
    __shared__ float ws[32][65];
    int ct = blockIdx.x, sp = blockIdx.y;
    int t = threadIdx.x;
    int tn = t & 15, tc = t >> 4;
    float acc[2][4];
#pragma unroll
    for (int i = 0; i < 2; i++)
#pragma unroll
        for (int j = 0; j < 4; j++) acc[i][j] = 0.f;

    int j0 = sp * 128;
    for (int k0 = j0; k0 < j0 + 128; k0 += 32) {
        __syncthreads();
#pragma unroll
        for (int i = 0; i < 4; i++) {
            int idx = t + i * 256;
            int n = idx >> 5, kk = idx & 31;
            fs[kk][n] = g_f[(size_t)n * 9216 + k0 + kk];
        }
#pragma unroll
        for (int i = 0; i < 8; i++) {
            int idx = t + i * 256;
            int c = idx >> 5, kk = idx & 31;
            ws[kk][c] = w1[(size_t)(ct * 64 + c) * 9216 + k0 + kk];
        }
        __syncthreads();
#pragma unroll
        for (int kk = 0; kk < 32; kk++) {
            float fv[2], wv[4];
            fv[0] = fs[kk][tn * 2];
            fv[1] = fs[kk][tn * 2 + 1];
#pragma unroll
            for (int j = 0; j < 4; j++) wv[j] = ws[kk][tc * 4 + j];
#pragma unroll
            for (int i = 0; i < 2; i++)
#pragma unroll
                for (int j = 0; j < 4; j++) acc[i][j] += fv[i] * wv[j];
        }
    }
#pragma unroll
    for (int i = 0; i < 2; i++)
#pragma unroll
        for (int j = 0; j < 4; j++)
            g_cpart[(size_t)(sp * 256 + ct * 64 + tc * 4 + j) * 32 + tn * 2 + i] =
                acc[i][j];
}

// -------- Kernel C2: reduce splits, bias, relu, split to fp16 [n][c] --------
__global__ void kC2(const float* __restrict__ b1) {
    int idx = blockIdx.x * 256 + threadIdx.x;  // 8192 = 256c * 32n
    int c = idx >> 5, n = idx & 31;
    float a = b1[c];
#pragma unroll
    for (int sp = 0; sp < 72; sp++) a += g_cpart[(size_t)(sp * 256 + c) * 32 + n];
    a = fmaxf(a, 0.f);
    __half hi = __float2half(a);
    g_h1h[n * 256 + c] = hi;
    g_h1l[n * 256 + c] = __float2half(a - __half2float(hi));
}

// ====== kD_mma: h2 = h1 @ w2^T; fp16 2-term; 4-deep cp.async w2 ring ========
#define WSTR 36
#define BSTR 40
#define KD_WST 0                              // 4 x 128 x WSTR fp32 = 73728 B
#define KD_AH  73728                          // 32 x BSTR fp16 = 2560 B
#define KD_AL  (KD_AH + 2560)
#define KD_BH  (KD_AL + 2560)                 // 128 x BSTR fp16 = 10240 B
#define KD_SM  (KD_BH + 10240)
#define KD_SMEM (KD_SM + 256)
__global__ void __launch_bounds__(256, 2) kD_mma(const float* __restrict__ w2,
                                                 const float* __restrict__ b2) {
    extern __shared__ char dsm[];
    uint32_t sb = smem_u32(dsm);
    float* Wst = (float*)dsm;
    __half* Bh = (__half*)(dsm + KD_BH);
    __half* Ah = (__half*)(dsm + KD_AH);
    __half* Al = (__half*)(dsm + KD_AL);
    float* sm1 = (float*)(dsm + KD_SM);
    float* sm2 = sm1 + 32;

    int t = threadIdx.x, lane = t & 31, wid = t >> 5;
    int bo = blockIdx.x * 128;
    if (t < 32) { sm1[t] = 0.f; sm2[t] = 0.f; }

    float acc[2][2][4];
#pragma unroll
    for (int i = 0; i < 2; i++)
#pragma unroll
        for (int j = 0; j < 2; j++)
#pragma unroll
            for (int kq = 0; kq < 4; kq++) acc[i][j][kq] = 0.f;

    uint32_t sAh = sb + KD_AH, sAl = sb + KD_AL, sBh = sb + KD_BH;

    int a_row = lane & 15;
    int a_koff = (lane >> 4) * 8;
    int b_row = wid * 16 + (lane & 7) + ((lane >> 4) & 1) * 8;
    int b_koff = ((lane >> 3) & 1) * 8;

    auto issueW = [&](int buf, int chunk) {
#pragma unroll
        for (int i = 0; i < 4; i++) {
            int idx = t + i * 256;
            int r = idx >> 3, q = idx & 7;
            cpa16(sb + KD_WST + (uint32_t)(buf * 128 * WSTR + r * WSTR + q * 4) * 4,
                  w2 + (size_t)(bo + r) * 256 + chunk * 32 + q * 4);
        }
        CP_COMMIT();
    };

    issueW(0, 0); issueW(1, 1); issueW(2, 2);
    for (int chunk = 0; chunk < 8; chunk++) {
        int k0 = chunk * 32;
        CP_WAIT2();
        __syncthreads();
        if (chunk + 3 < 8) issueW((chunk + 3) & 3, chunk + 3);
        else CP_COMMIT();                      // keep FIFO group count exact
        // A: 32 rows x 32 fp16 per split
        if (t < 128) {
            int r = t >> 2, q = t & 3;
            *(uint4*)&Ah[r * BSTR + q * 8] = *(const uint4*)&g_h1h[r * 256 + k0 + q * 8];
            *(uint4*)&Al[r * BSTR + q * 8] = *(const uint4*)&g_h1l[r * 256 + k0 + q * 8];
        }
        // convert staged fp32 w2 -> fp16 Bh
        const float* Wb = Wst + (chunk & 3) * 128 * WSTR;
#pragma unroll
        for (int i = 0; i < 4; i++) {
            int idx = t + i * 256;
            int r = idx >> 3, q = idx & 7;
            float4 v = *(const float4*)&Wb[r * WSTR + q * 4];
            __half2 p01 = __floats2half2_rn(v.x, v.y);
            __half2 p23 = __floats2half2_rn(v.z, v.w);
            *(uint2*)&Bh[r * BSTR + q * 4] =
                make_uint2(*(uint32_t*)&p01, *(uint32_t*)&p23);
        }
        __syncthreads();

#pragma unroll
        for (int ks = 0; ks < 2; ks++) {
            uint32_t ah[2][4], al[2][4];
#pragma unroll
            for (int im = 0; im < 2; im++) {
                uint32_t off = ((a_row + im * 16) * BSTR + ks * 16 + a_koff) * 2;
                ldm_x4(ah[im], sAh + off);
                ldm_x4(al[im], sAl + off);
            }
            uint32_t bh[4];
            {
                uint32_t off = (b_row * BSTR + ks * 16 + b_koff) * 2;
                ldm_x4(bh, sBh + off);
            }
#pragma unroll
            for (int im = 0; im < 2; im++)
#pragma unroll
                for (int j = 0; j < 2; j++) {
                    const uint32_t* ph = bh + j * 2;
                    mma_f16(acc[im][j], ah[im], ph);
                    mma_f16(acc[im][j], al[im], ph);
                }
        }
    }

    int g = lane >> 2, t4 = lane & 3;
#pragma unroll
    for (int j = 0; j < 2; j++) {
        int o = bo + wid * 16 + j * 8 + t4 * 2;
        float bb0 = b2[o], bb1 = b2[o + 1];
#pragma unroll
        for (int im = 0; im < 2; im++) {
            int n0 = im * 16 + g, n1 = n0 + 8;
            float v0 = acc[im][j][0] + bb0, v1 = acc[im][j][1] + bb1;
            float v2 = acc[im][j][2] + bb0, v3 = acc[im][j][3] + bb1;
            *(float2*)&g_h2[(size_t)n0 * 131072 + o] = make_float2(v0, v1);
            *(float2*)&g_h2[(size_t)n1 * 131072 + o] = make_float2(v2, v3);
            atomicAdd(&sm1[n0], v0 + v1);
            atomicAdd(&sm2[n0], v0 * v0 + v1 * v1);
            atomicAdd(&sm1[n1], v2 + v3);
            atomicAdd(&sm2[n1], v2 * v2 + v3 * v3);
        }
    }
    __syncthreads();
    if (t < 32) {
        g_dp1[(size_t)blockIdx.x * 32 + t] = sm1[t];
        g_dp2[(size_t)blockIdx.x * 32 + t] = sm2[t];
    }
}

// ---------------- Kernel D2: finish LN stats over 131072/row ----------------
__global__ void kD2() {
    int n = blockIdx.x;
    float s = 0.f, q = 0.f;
    for (int b = threadIdx.x; b < 1024; b += 256) {
        s += g_dp1[(size_t)b * 32 + n];
        q += g_dp2[(size_t)b * 32 + n];
    }
#pragma unroll
    for (int off = 16; off; off >>= 1) {
        s += __shfl_down_sync(0xFFFFFFFFu, s, off);
        q += __shfl_down_sync(0xFFFFFFFFu, q, off);
    }
    __shared__ float sh[16];
    int wv = threadIdx.x >> 5, lane = threadIdx.x & 31;
    if (lane == 0) { sh[wv] = s; sh[wv + 8] = q; }
    __syncthreads();
    if (threadIdx.x == 0) {
        float S = 0.f, Q = 0.f;
        for (int i = 0; i < 8; i++) { S += sh[i]; Q += sh[i + 8]; }
        float mu = S / 131072.f;
        float var = Q / 131072.f - mu * mu;
        g_stats[n * 2] = mu;
        g_stats[n * 2 + 1] = rsqrtf(var + EPSV);
    }
}

// ====== kE0: y = LN(h2) transposed [n][l][c], single fp16 ===================
__global__ void kE0(const float* __restrict__ g2, const float* __restrict__ be2) {
    __shared__ float tile[32][33];
    int c0 = blockIdx.x * 32, l0 = blockIdx.y * 32, n = blockIdx.z;
    int tx = threadIdx.x, ty = threadIdx.y;
    float mu = g_stats[n * 2], rstd = g_stats[n * 2 + 1];
    const float* h2n = g_h2 + (size_t)n * 131072;
#pragma unroll
    for (int k = 0; k < 4; k++) {
        int gidx = (c0 + ty + k * 8) * 1024 + l0 + tx;
        tile[ty + k * 8][tx] = (h2n[gidx] - mu) * rstd * g2[gidx] + be2[gidx];
    }
    __syncthreads();
#pragma unroll
    for (int k = 0; k < 4; k++) {
        int l = l0 + ty + k * 8, c = c0 + tx;
        g_yh[((size_t)n * 1024 + l) * 128 + c] = __float2half(tile[tx][ty + k * 8]);
    }
}

// ====== kE_mma: out = BN(w_out @ y) + x; pure fp16; cp.async 3-stage ========
__global__ void __launch_bounds__(256, 2) kE_mma(
    const float* __restrict__ bng, const float* __restrict__ bnb,
    const float* __restrict__ bnm, const float* __restrict__ bnv,
    const float* __restrict__ x, float* __restrict__ out) {
    extern __shared__ char dsm[];
    uint32_t sb = smem_u32(dsm);

    int t = threadIdx.x, lane = t & 31, wid = t >> 5;
    int warp_m = wid & 3, warp_n = wid >> 2;
    int lt = blockIdx.x, ot = blockIdx.y, n = blockIdx.z;

    float acc[2][8][4];
#pragma unroll
    for (int i = 0; i < 2; i++)
#pragma unroll
        for (int j = 0; j < 8; j++)
#pragma unroll
            for (int kq = 0; kq < 4; kq++) acc[i][j][kq] = 0.f;

    int a_row = warp_m * 32 + (lane & 15);
    int a_koff = (lane >> 4) * 8;
    int b_row = warp_n * 64 + (lane & 7) + ((lane >> 4) & 1) * 8;
    int b_koff = ((lane >> 3) & 1) * 8;

    int r = t >> 2, q = t & 3;
    uint32_t so = (uint32_t)(r * ASTR + q * 8) * 2;
    uint32_t so2 = (uint32_t)((r + 64) * ASTR + q * 8) * 2;

    auto issue = [&](int buf, int chunk) {
        uint32_t base = sb + buf * BUF_B;
        int acol = chunk * 32;
        size_t goA = (size_t)(ot * 128 + r) * 128 + acol + q * 8;
        cpa16(base + OFFAH + so, g_voh + goA);
        cpa16(base + OFFAH + so2, g_voh + goA + 64 * 128);
        size_t goB = ((size_t)n * 1024 + lt * 128 + r) * 128 + acol + q * 8;
        cpa16(base + OFFBH + so, g_yh + goB);
        cpa16(base + OFFBH + so2, g_yh + goB + 64 * 128);
        CP_COMMIT();
    };

    issue(0, 0); issue(1, 1);
    int buf = 0;
    for (int chunk = 0; chunk < 4; chunk++) {
        CP_WAIT1();
        __syncthreads();
        if (chunk + 2 < 4) {
            int nb = buf + 2; if (nb >= 3) nb -= 3;
            issue(nb, chunk + 2);
        } else CP_COMMIT();
        uint32_t base = sb + buf * BUF_B;
        uint32_t sAh = base + OFFAH, sBh = base + OFFBH;

#pragma unroll
        for (int ks = 0; ks < 2; ks++) {
            uint32_t ah[2][4];
#pragma unroll
            for (int im = 0; im < 2; im++) {
                uint32_t off = ((a_row + im * 16) * ASTR + ks * 16 + a_koff) * 2;
                ldm_x4(ah[im], sAh + off);
            }
            uint32_t bh[4][4];
#pragma unroll
            for (int jn = 0; jn < 4; jn++) {
                uint32_t off = ((b_row + jn * 16) * ASTR + ks * 16 + b_koff) * 2;
                ldm_x4(bh[jn], sBh + off);
            }
#pragma unroll
            for (int im = 0; im < 2; im++)
#pragma unroll
                for (int jb = 0; jb < 8; jb++) {
                    const uint32_t* ph = bh[jb >> 1] + (jb & 1) * 2;
                    mma_f16(acc[im][jb], ah[im], ph);
                }
        }
        if (++buf >= 3) buf = 0;
    }

    int g = lane >> 2, t4 = lane & 3;
#pragma unroll
    for (int im = 0; im < 2; im++) {
        int oa = ot * 128 + warp_m * 32 + im * 16 + g;
        int ob = oa + 8;
        float scA = bng[oa] * rsqrtf(bnv[oa] + EPSV);
        float scB = bng[ob] * rsqrtf(bnv[ob] + EPSV);
        float mbA = bnm[oa], bbA = bnb[oa];
        float mbB = bnm[ob], bbB = bnb[ob];
        const float* xa = x + ((size_t)n * 256 + oa) * 1024;
        const float* xb = x + ((size_t)n * 256 + ob) * 1024;
        float* pa = out + ((size_t)n * 256 + oa) * 1024;
        float* pb = out + ((size_t)n * 256 + ob) * 1024;
#pragma unroll
        for (int jb = 0; jb < 8; jb++) {
            int l = lt * 128 + warp_n * 64 + jb * 8 + t4 * 2;
            float2 xva = *(const float2*)&xa[l];
            float2 xvb = *(const float2*)&xb[l];
            float2 ra, rb;
            ra.x = (acc[im][jb][0] - mbA) * scA + bbA + xva.x;
            ra.y = (acc[im][jb][1] - mbA) * scA + bbA + xva.y;
            rb.x = (acc[im][jb][2] - mbB) * scB + bbB + xvb.x;
            rb.y = (acc[im][jb][3] - mbB) * scB + bbB + xvb.y;
            *(float2*)&pa[l] = ra;
            *(float2*)&pb[l] = rb;
        }
    }
}

// ============================== launcher ====================================
extern "C" void kernel_launch(void* const* d_in, const int* in_sizes, int n_in,
                              void* d_out, int out_size) {
    const float* x    = (const float*)d_in[0];
    const float* wq   = (const float*)d_in[1];
    const float* wk   = (const float*)d_in[2];
    const float* g1   = (const float*)d_in[3];
    const float* be1  = (const float*)d_in[4];
    const float* w1   = (const float*)d_in[5];
    const float* b1   = (const float*)d_in[6];
    const float* w2   = (const float*)d_in[7];
    const float* b2   = (const float*)d_in[8];
    const float* g2   = (const float*)d_in[9];
    const float* be2  = (const float*)d_in[10];
    const float* wout = (const float*)d_in[11];
    const float* bng  = (const float*)d_in[12];
    const float* bnb  = (const float*)d_in[13];
    const float* bnm  = (const float*)d_in[14];
    const float* bnv  = (const float*)d_in[15];
    float* out = (float*)d_out;

    static bool attr_done = false;
    if (!attr_done) {
        cudaFuncSetAttribute(kA2, cudaFuncAttributeMaxDynamicSharedMemorySize,
                             3 * BUF_B);
        cudaFuncSetAttribute(kE_mma, cudaFuncAttributeMaxDynamicSharedMemorySize,
                             3 * BUF_B);
        cudaFuncSetAttribute(kD_mma, cudaFuncAttributeMaxDynamicSharedMemorySize,
                             KD_SMEM);
        attr_done = true;
    }

    kWV<<<384, 256>>>(wq, wk, wout);
    kT<<<dim3(8, 32, 32), dim3(32, 8)>>>(x);
    kA2<<<dim3(8, 2, 32), 256, 3 * BUF_B>>>();
    kB<<<dim3(32, 32, 2), 288>>>();
    kB2<<<32, 256>>>(g1, be1);
    kC<<<dim3(4, 72), 256>>>(w1);
    kC2<<<32, 256>>>(b1);
    kD_mma<<<1024, 256, KD_SMEM>>>(w2, b2);
    kD2<<<32, 256>>>();
    kE0<<<dim3(4, 32, 32), dim3(32, 8)>>>(g2, be2);
    kE_mma<<<dim3(8, 2, 32), 256, 3 * BUF_B>>>(bng, bnb, bnm, bnv, x, out);
}

// round 17
// speedup vs baseline: 1.2173x; 1.0467x over previous
#include <cuda_runtime.h>
#include <cuda_bf16.h>
#include <cuda_fp16.h>
#include <cstdint>

#define EPSV 1e-5f

// ---------------- scratch (device globals; no allocation allowed) ----------
__device__ __align__(16) __half g_qkh[32u * 256u * 1024u]; // [n][o][l] fp16
__device__ float g_f [32u * 9216u];          // [n][r*1024 + l]; kB accumulates
__device__ float g_cpart[72u * 256u * 32u];  // [ksplit][c][n]
__device__ float g_h2[32u * 131072u];        // [n][o]
__device__ float g_dp1[2048u * 32u];
__device__ float g_dp2[2048u * 32u];
__device__ float g_stats[32u * 2u];

// fp16 operands
__device__ __align__(16) __half g_wh[256u * 256u];        // [o][c]
__device__ __align__(16) __half g_xh[32u * 1024u * 256u]; // [n][l][c]
__device__ __align__(16) __half g_h1h[32u * 256u];        // [n][c]
__device__ __align__(16) __half g_yh[32u * 1024u * 128u]; // [n][l][c]
__device__ __align__(16) __half g_voh[256u * 128u];       // [o][c]

// ======================= warp-MMA helpers ==================================
__device__ __forceinline__ uint32_t smem_u32(const void* p) {
    uint32_t a;
    asm("{ .reg .u64 t; cvta.to.shared.u64 t, %1; cvt.u32.u64 %0, t; }"
        : "=r"(a) : "l"(p));
    return a;
}
__device__ __forceinline__ void ldm_x4(uint32_t* r, uint32_t addr) {
    asm volatile("ldmatrix.sync.aligned.m8n8.x4.shared.b16 {%0,%1,%2,%3}, [%4];"
                 : "=r"(r[0]), "=r"(r[1]), "=r"(r[2]), "=r"(r[3]) : "r"(addr));
}
__device__ __forceinline__ void mma_f16(float* d, const uint32_t* a,
                                        const uint32_t* b) {
    asm volatile(
        "mma.sync.aligned.m16n8k16.row.col.f32.f16.f16.f32 "
        "{%0,%1,%2,%3}, {%4,%5,%6,%7}, {%8,%9}, {%0,%1,%2,%3};"
        : "+f"(d[0]), "+f"(d[1]), "+f"(d[2]), "+f"(d[3])
        : "r"(a[0]), "r"(a[1]), "r"(a[2]), "r"(a[3]), "r"(b[0]), "r"(b[1]));
}
__device__ __forceinline__ void cpa16(uint32_t dst, const void* src) {
    asm volatile("cp.async.cg.shared.global [%0], [%1], 16;"
                 :: "r"(dst), "l"(src));
}
#define CP_COMMIT() asm volatile("cp.async.commit_group;" ::: "memory")
#define CP_WAIT1()  asm volatile("cp.async.wait_group 1;" ::: "memory")
#define CP_WAIT2()  asm volatile("cp.async.wait_group 2;" ::: "memory")

// ==== kWV: convert concat(wq,wk)+w_out to fp16; zero g_f ====================
__global__ void kWV(const float* __restrict__ wq, const float* __restrict__ wk,
                    const float* __restrict__ wout) {
    int idx = blockIdx.x * 256 + threadIdx.x;   // 98304 threads
    if (idx < 65536) {
        int o = idx >> 8, c = idx & 255;
        float v = (o < 128) ? wq[o * 256 + c] : wk[(o - 128) * 256 + c];
        g_wh[idx] = __float2half(v);
    } else {
        int j = idx - 65536;
        g_voh[j] = __float2half(wout[j]);
    }
    g_f[idx] = 0.f;
    g_f[idx + 98304] = 0.f;
    g_f[idx + 196608] = 0.f;
}

// ====== kT: transpose x[n][c][l] -> xT[n][l][c], single fp16 ================
__global__ void kT(const float* __restrict__ x) {
    __shared__ float tile[32][33];
    int c0 = blockIdx.x * 32, l0 = blockIdx.y * 32, n = blockIdx.z;
    int tx = threadIdx.x, ty = threadIdx.y;
    const float* xn = x + (size_t)n * 256 * 1024;
#pragma unroll
    for (int k = 0; k < 4; k++)
        tile[ty + k * 8][tx] = xn[(size_t)(c0 + ty + k * 8) * 1024 + l0 + tx];
    __syncthreads();
#pragma unroll
    for (int k = 0; k < 4; k++) {
        int l = l0 + ty + k * 8, c = c0 + tx;
        g_xh[((size_t)n * 1024 + l) * 256 + c] = __float2half(tile[tx][ty + k * 8]);
    }
}

// ====== kA2: qk = W @ x, pure fp16, cp.async 3-stage ========================
#define ASTR 40
#define TILE_B 10240                        // one 128xASTR fp16 tile bytes
#define BUF_B  (2 * TILE_B)                 // Ah, Bh per stage
#define OFFAH 0
#define OFFBH TILE_B
__global__ void __launch_bounds__(256, 2) kA2() {
    extern __shared__ char dsm[];
    uint32_t sb = smem_u32(dsm);

    int t = threadIdx.x, lane = t & 31, wid = t >> 5;
    int warp_m = wid & 3, warp_n = wid >> 2;
    int lt = blockIdx.x, ot = blockIdx.y, n = blockIdx.z;

    float acc[2][8][4];
#pragma unroll
    for (int i = 0; i < 2; i++)
#pragma unroll
        for (int j = 0; j < 8; j++)
#pragma unroll
            for (int kq = 0; kq < 4; kq++) acc[i][j][kq] = 0.f;

    int a_row = warp_m * 32 + (lane & 15);
    int a_koff = (lane >> 4) * 8;
    int b_row = warp_n * 64 + (lane & 7) + ((lane >> 4) & 1) * 8;
    int b_koff = ((lane >> 3) & 1) * 8;

    int r = t >> 2, q = t & 3;
    uint32_t so = (uint32_t)(r * ASTR + q * 8) * 2;
    uint32_t so2 = (uint32_t)((r + 64) * ASTR + q * 8) * 2;

    auto issue = [&](int buf, int chunk) {
        uint32_t base = sb + buf * BUF_B;
        int acol = chunk * 32;
        size_t goA = (size_t)(ot * 128 + r) * 256 + acol + q * 8;
        cpa16(base + OFFAH + so, g_wh + goA);
        cpa16(base + OFFAH + so2, g_wh + goA + 64 * 256);
        size_t goB = ((size_t)n * 1024 + lt * 128 + r) * 256 + acol + q * 8;
        cpa16(base + OFFBH + so, g_xh + goB);
        cpa16(base + OFFBH + so2, g_xh + goB + 64 * 256);
        CP_COMMIT();
    };

    issue(0, 0); issue(1, 1);
    int buf = 0;
    for (int chunk = 0; chunk < 8; chunk++) {
        CP_WAIT1();
        __syncthreads();
        if (chunk + 2 < 8) {
            int nb = buf + 2; if (nb >= 3) nb -= 3;
            issue(nb, chunk + 2);
        } else CP_COMMIT();
        uint32_t base = sb + buf * BUF_B;
        uint32_t sAh = base + OFFAH, sBh = base + OFFBH;

#pragma unroll
        for (int ks = 0; ks < 2; ks++) {
            uint32_t ah[2][4];
#pragma unroll
            for (int im = 0; im < 2; im++) {
                uint32_t off = ((a_row + im * 16) * ASTR + ks * 16 + a_koff) * 2;
                ldm_x4(ah[im], sAh + off);
            }
            uint32_t bh[4][4];
#pragma unroll
            for (int jn = 0; jn < 4; jn++) {
                uint32_t off = ((b_row + jn * 16) * ASTR + ks * 16 + b_koff) * 2;
                ldm_x4(bh[jn], sBh + off);
            }
#pragma unroll
            for (int im = 0; im < 2; im++)
#pragma unroll
                for (int jb = 0; jb < 8; jb++) {
                    const uint32_t* ph = bh[jb >> 1] + (jb & 1) * 2;
                    mma_f16(acc[im][jb], ah[im], ph);
                }
        }
        if (++buf >= 3) buf = 0;
    }

    int g = lane >> 2, t4 = lane & 3;
#pragma unroll
    for (int im = 0; im < 2; im++) {
        int o0 = ot * 128 + warp_m * 32 + im * 16 + g;
#pragma unroll
        for (int jb = 0; jb < 8; jb++) {
            int l = lt * 128 + warp_n * 64 + jb * 8 + t4 * 2;
            __half2 h0 = __floats2half2_rn(acc[im][jb][0], acc[im][jb][1]);
            __half2 h1 = __floats2half2_rn(acc[im][jb][2], acc[im][jb][3]);
            *(__half2*)&g_qkh[((size_t)n * 256 + o0) * 1024 + l] = h0;
            *(__half2*)&g_qkh[((size_t)n * 256 + o0 + 8) * 1024 + l] = h1;
        }
    }
}

// ============ Kernel B: partial f over 64-channel chunk, REDG into g_f ======
__global__ void kB() {
    int h = blockIdx.x, n = blockIdx.y, cs = blockIdx.z;
    __shared__ float4 qs[16][32];    // 8 KB
    __shared__ float4 ks[16][102];   // 25.5 KB
    int t = threadIdx.x;
    int r = t >> 5, w = t & 31;
    int c0 = cs * 64;
    const __half* qn = g_qkh + (size_t)n * 256 * 1024;
    const __half* kn = qn + 128u * 1024u;
    int hh = r / 3, dw = r % 3;
    int kidx = hh * 34 + w + dw;

    for (int idx = t; idx < 16 * 32; idx += 288) {
        int cc = idx >> 5, ww = idx & 31;
        const __half* b = qn + (size_t)(c0 + cc) * 1024 + h * 32 + ww;
        qs[cc][ww] = make_float4(__half2float(b[0]),
                                 __half2float(b[16 * 1024]),
                                 __half2float(b[32 * 1024]),
                                 __half2float(b[48 * 1024]));
    }
    for (int idx = t; idx < 16 * 102; idx += 288) {
        int cc = idx / 102, rem = idx % 102;
        int rr = rem / 34, ww = rem % 34;
        int hg = h + rr - 1, wg = ww - 1;
        float4 v = make_float4(0.f, 0.f, 0.f, 0.f);
        if (hg >= 0 && hg < 32 && wg >= 0 && wg < 32) {
            const __half* b = kn + (size_t)(c0 + cc) * 1024 + hg * 32 + wg;
            v = make_float4(__half2float(b[0]),
                            __half2float(b[16 * 1024]),
                            __half2float(b[32 * 1024]),
                            __half2float(b[48 * 1024]));
        }
        ks[cc][rem] = v;
    }
    __syncthreads();
    float a0 = 0.f, a1 = 0.f, a2 = 0.f, a3 = 0.f;
#pragma unroll
    for (int cc = 0; cc < 16; cc++) {
        float4 qv = qs[cc][w];
        float4 kv = ks[cc][kidx];
        a0 += qv.x * kv.x;
        a1 += qv.y * kv.y;
        a2 += qv.z * kv.z;
        a3 += qv.w * kv.w;
    }
    atomicAdd(&g_f[(size_t)n * 9216 + r * 1024 + h * 32 + w],
              (a0 + a1) + (a2 + a3));
}

// ========== Kernel B2: x2 + layernorm rows of f (in place) ==================
__global__ void kB2(const float* __restrict__ g1, const float* __restrict__ be1) {
    int n = blockIdx.x;
    float* f = g_f + (size_t)n * 9216;
    float s = 0.f, q = 0.f;
    for (int j = threadIdx.x; j < 9216; j += 256) {
        float v = 2.f * f[j];
        s += v; q += v * v;
    }
#pragma unroll
    for (int off = 16; off; off >>= 1) {
        s += __shfl_down_sync(0xFFFFFFFFu, s, off);
        q += __shfl_down_sync(0xFFFFFFFFu, q, off);
    }
    __shared__ float sh[34];
    int wv = threadIdx.x >> 5, lane = threadIdx.x & 31;
    if (lane == 0) { sh[wv] = s; sh[wv + 8] = q; }
    __syncthreads();
    if (threadIdx.x == 0) {
        float S = 0.f, Q = 0.f;
        for (int i = 0; i < 8; i++) { S += sh[i]; Q += sh[i + 8]; }
        float mu = S / 9216.f;
        float var = Q / 9216.f - mu * mu;
        sh[32] = mu;
        sh[33] = rsqrtf(var + EPSV);
    }
    __syncthreads();
    float mu = sh[32], rstd = sh[33];
    for (int j = threadIdx.x; j < 9216; j += 256)
        f[j] = (2.f * f[j] - mu) * rstd * g1[j] + be1[j];
}

// ===== Kernel C: split-K tiled GEMM: h1[n,c] partials, 72 K-slices ==========
__global__ void kC(const float* __restrict__ w1) {
    __shared__ float fs[32][33];
    __shared__ float ws[32][65];
    int ct = blockIdx.x, sp = blockIdx.y;
    int t = threadIdx.x;
    int tn = t & 15, tc = t >> 4;
    float acc[2][4];
#pragma unroll
    for (int i = 0; i < 2; i++)
#pragma unroll
        for (int j = 0; j < 4; j++) acc[i][j] = 0.f;

    int j0 = sp * 128;
    for (int k0 = j0; k0 < j0 + 128; k0 += 32) {
        __syncthreads();
#pragma unroll
        for (int i = 0; i < 4; i++) {
            int idx = t + i * 256;
            int n = idx >> 5, kk = idx & 31;
            fs[kk][n] = g_f[(size_t)n * 9216 + k0 + kk];
        }
#pragma unroll
        for (int i = 0; i < 8; i++) {
            int idx = t + i * 256;
            int c = idx >> 5, kk = idx & 31;
            ws[kk][c] = w1[(size_t)(ct * 64 + c) * 9216 + k0 + kk];
        }
        __syncthreads();
#pragma unroll
        for (int kk = 0; kk < 32; kk++) {
            float fv[2], wv[4];
            fv[0] = fs[kk][tn * 2];
            fv[1] = fs[kk][tn * 2 + 1];
#pragma unroll
            for (int j = 0; j < 4; j++) wv[j] = ws[kk][tc * 4 + j];
#pragma unroll
            for (int i = 0; i < 2; i++)
#pragma unroll
                for (int j = 0; j < 4; j++) acc[i][j] += fv[i] * wv[j];
        }
    }
#pragma unroll
    for (int i = 0; i < 2; i++)
#pragma unroll
        for (int j = 0; j < 4; j++)
            g_cpart[(size_t)(sp * 256 + ct * 64 + tc * 4 + j) * 32 + tn * 2 + i] =
                acc[i][j];
}

// -------- Kernel C2: reduce splits, bias, relu, fp16 [n][c] -----------------
__global__ void kC2(const float* __restrict__ b1) {
    int idx = blockIdx.x * 256 + threadIdx.x;  // 8192 = 256c * 32n
    int c = idx >> 5, n = idx & 31;
    float a = b1[c];
#pragma unroll
    for (int sp = 0; sp < 72; sp++) a += g_cpart[(size_t)(sp * 256 + c) * 32 + n];
    a = fmaxf(a, 0.f);
    g_h1h[n * 256 + c] = __float2half(a);
}

// ====== kD_mma: h2 = h1 @ w2^T; pure fp16; 4-deep cp.async w2 ring ==========
#define WSTR 36
#define BSTR 40
#define KD_WST 0                              // 4 x 128 x WSTR fp32 = 73728 B
#define KD_AH  73728                          // 32 x BSTR fp16 = 2560 B
#define KD_BH  (KD_AH + 2560)                 // 128 x BSTR fp16 = 10240 B
#define KD_SM  (KD_BH + 10240)
#define KD_SMEM (KD_SM + 256)
__global__ void __launch_bounds__(256, 2) kD_mma(const float* __restrict__ w2,
                                                 const float* __restrict__ b2) {
    extern __shared__ char dsm[];
    uint32_t sb = smem_u32(dsm);
    float* Wst = (float*)dsm;
    __half* Bh = (__half*)(dsm + KD_BH);
    __half* Ah = (__half*)(dsm + KD_AH);
    float* sm1 = (float*)(dsm + KD_SM);
    float* sm2 = sm1 + 32;

    int t = threadIdx.x, lane = t & 31, wid = t >> 5;
    int bo = blockIdx.x * 128;
    if (t < 32) { sm1[t] = 0.f; sm2[t] = 0.f; }

    float acc[2][2][4];
#pragma unroll
    for (int i = 0; i < 2; i++)
#pragma unroll
        for (int j = 0; j < 2; j++)
#pragma unroll
            for (int kq = 0; kq < 4; kq++) acc[i][j][kq] = 0.f;

    uint32_t sAh = sb + KD_AH, sBh = sb + KD_BH;

    int a_row = lane & 15;
    int a_koff = (lane >> 4) * 8;
    int b_row = wid * 16 + (lane & 7) + ((lane >> 4) & 1) * 8;
    int b_koff = ((lane >> 3) & 1) * 8;

    auto issueW = [&](int buf, int chunk) {
#pragma unroll
        for (int i = 0; i < 4; i++) {
            int idx = t + i * 256;
            int r = idx >> 3, q = idx & 7;
            cpa16(sb + KD_WST + (uint32_t)(buf * 128 * WSTR + r * WSTR + q * 4) * 4,
                  w2 + (size_t)(bo + r) * 256 + chunk * 32 + q * 4);
        }
        CP_COMMIT();
    };

    issueW(0, 0); issueW(1, 1); issueW(2, 2);
    for (int chunk = 0; chunk < 8; chunk++) {
        int k0 = chunk * 32;
        CP_WAIT2();
        __syncthreads();
        if (chunk + 3 < 8) issueW((chunk + 3) & 3, chunk + 3);
        else CP_COMMIT();                      // keep FIFO group count exact
        // A: 32 rows x 32 fp16
        if (t < 128) {
            int r = t >> 2, q = t & 3;
            *(uint4*)&Ah[r * BSTR + q * 8] = *(const uint4*)&g_h1h[r * 256 + k0 + q * 8];
        }
        // convert staged fp32 w2 -> fp16 Bh
        const float* Wb = Wst + (chunk & 3) * 128 * WSTR;
#pragma unroll
        for (int i = 0; i < 4; i++) {
            int idx = t + i * 256;
            int r = idx >> 3, q = idx & 7;
            float4 v = *(const float4*)&Wb[r * WSTR + q * 4];
            __half2 p01 = __floats2half2_rn(v.x, v.y);
            __half2 p23 = __floats2half2_rn(v.z, v.w);
            *(uint2*)&Bh[r * BSTR + q * 4] =
                make_uint2(*(uint32_t*)&p01, *(uint32_t*)&p23);
        }
        __syncthreads();

#pragma unroll
        for (int ks = 0; ks < 2; ks++) {
            uint32_t ah[2][4];
#pragma unroll
            for (int im = 0; im < 2; im++) {
                uint32_t off = ((a_row + im * 16) * BSTR + ks * 16 + a_koff) * 2;
                ldm_x4(ah[im], sAh + off);
            }
            uint32_t bh[4];
            {
                uint32_t off = (b_row * BSTR + ks * 16 + b_koff) * 2;
                ldm_x4(bh, sBh + off);
            }
#pragma unroll
            for (int im = 0; im < 2; im++)
#pragma unroll
                for (int j = 0; j < 2; j++) {
                    const uint32_t* ph = bh + j * 2;
                    mma_f16(acc[im][j], ah[im], ph);
                }
        }
    }

    int g = lane >> 2, t4 = lane & 3;
#pragma unroll
    for (int j = 0; j < 2; j++) {
        int o = bo + wid * 16 + j * 8 + t4 * 2;
        float bb0 = b2[o], bb1 = b2[o + 1];
#pragma unroll
        for (int im = 0; im < 2; im++) {
            int n0 = im * 16 + g, n1 = n0 + 8;
            float v0 = acc[im][j][0] + bb0, v1 = acc[im][j][1] + bb1;
            float v2 = acc[im][j][2] + bb0, v3 = acc[im][j][3] + bb1;
            *(float2*)&g_h2[(size_t)n0 * 131072 + o] = make_float2(v0, v1);
            *(float2*)&g_h2[(size_t)n1 * 131072 + o] = make_float2(v2, v3);
            atomicAdd(&sm1[n0], v0 + v1);
            atomicAdd(&sm2[n0], v0 * v0 + v1 * v1);
            atomicAdd(&sm1[n1], v2 + v3);
            atomicAdd(&sm2[n1], v2 * v2 + v3 * v3);
        }
    }
    __syncthreads();
    if (t < 32) {
        g_dp1[(size_t)blockIdx.x * 32 + t] = sm1[t];
        g_dp2[(size_t)blockIdx.x * 32 + t] = sm2[t];
    }
}

// ---------------- Kernel D2: finish LN stats over 131072/row ----------------
__global__ void kD2() {
    int n = blockIdx.x;
    float s = 0.f, q = 0.f;
    for (int b = threadIdx.x; b < 1024; b += 256) {
        s += g_dp1[(size_t)b * 32 + n];
        q += g_dp2[(size_t)b * 32 + n];
    }
#pragma unroll
    for (int off = 16; off; off >>= 1) {
        s += __shfl_down_sync(0xFFFFFFFFu, s, off);
        q += __shfl_down_sync(0xFFFFFFFFu, q, off);
    }
    __shared__ float sh[16];
    int wv = threadIdx.x >> 5, lane = threadIdx.x & 31;
    if (lane == 0) { sh[wv] = s; sh[wv + 8] = q; }
    __syncthreads();
    if (threadIdx.x == 0) {
        float S = 0.f, Q = 0.f;
        for (int i = 0; i < 8; i++) { S += sh[i]; Q += sh[i + 8]; }
        float mu = S / 131072.f;
        float var = Q / 131072.f - mu * mu;
        g_stats[n * 2] = mu;
        g_stats[n * 2 + 1] = rsqrtf(var + EPSV);
    }
}

// ====== kE0: y = LN(h2) transposed [n][l][c], single fp16 ===================
__global__ void kE0(const float* __restrict__ g2, const float* __restrict__ be2) {
    __shared__ float tile[32][33];
    int c0 = blockIdx.x * 32, l0 = blockIdx.y * 32, n = blockIdx.z;
    int tx = threadIdx.x, ty = threadIdx.y;
    float mu = g_stats[n * 2], rstd = g_stats[n * 2 + 1];
    const float* h2n = g_h2 + (size_t)n * 131072;
#pragma unroll
    for (int k = 0; k < 4; k++) {
        int gidx = (c0 + ty + k * 8) * 1024 + l0 + tx;
        tile[ty + k * 8][tx] = (h2n[gidx] - mu) * rstd * g2[gidx] + be2[gidx];
    }
    __syncthreads();
#pragma unroll
    for (int k = 0; k < 4; k++) {
        int l = l0 + ty + k * 8, c = c0 + tx;
        g_yh[((size_t)n * 1024 + l) * 128 + c] = __float2half(tile[tx][ty + k * 8]);
    }
}

// ====== kE_mma: out = BN(w_out @ y) + x; pure fp16; cp.async 3-stage ========
__global__ void __launch_bounds__(256, 2) kE_mma(
    const float* __restrict__ bng, const float* __restrict__ bnb,
    const float* __restrict__ bnm, const float* __restrict__ bnv,
    const float* __restrict__ x, float* __restrict__ out) {
    extern __shared__ char dsm[];
    uint32_t sb = smem_u32(dsm);

    int t = threadIdx.x, lane = t & 31, wid = t >> 5;
    int warp_m = wid & 3, warp_n = wid >> 2;
    int lt = blockIdx.x, ot = blockIdx.y, n = blockIdx.z;

    float acc[2][8][4];
#pragma unroll
    for (int i = 0; i < 2; i++)
#pragma unroll
        for (int j = 0; j < 8; j++)
#pragma unroll
            for (int kq = 0; kq < 4; kq++) acc[i][j][kq] = 0.f;

    int a_row = warp_m * 32 + (lane & 15);
    int a_koff = (lane >> 4) * 8;
    int b_row = warp_n * 64 + (lane & 7) + ((lane >> 4) & 1) * 8;
    int b_koff = ((lane >> 3) & 1) * 8;

    int r = t >> 2, q = t & 3;
    uint32_t so = (uint32_t)(r * ASTR + q * 8) * 2;
    uint32_t so2 = (uint32_t)((r + 64) * ASTR + q * 8) * 2;

    auto issue = [&](int buf, int chunk) {
        uint32_t base = sb + buf * BUF_B;
        int acol = chunk * 32;
        size_t goA = (size_t)(ot * 128 + r) * 128 + acol + q * 8;
        cpa16(base + OFFAH + so, g_voh + goA);
        cpa16(base + OFFAH + so2, g_voh + goA + 64 * 128);
        size_t goB = ((size_t)n * 1024 + lt * 128 + r) * 128 + acol + q * 8;
        cpa16(base + OFFBH + so, g_yh + goB);
        cpa16(base + OFFBH + so2, g_yh + goB + 64 * 128);
        CP_COMMIT();
    };

    issue(0, 0); issue(1, 1);
    int buf = 0;
    for (int chunk = 0; chunk < 4; chunk++) {
        CP_WAIT1();
        __syncthreads();
        if (chunk + 2 < 4) {
            int nb = buf + 2; if (nb >= 3) nb -= 3;
            issue(nb, chunk + 2);
        } else CP_COMMIT();
        uint32_t base = sb + buf * BUF_B;
        uint32_t sAh = base + OFFAH, sBh = base + OFFBH;

#pragma unroll
        for (int ks = 0; ks < 2; ks++) {
            uint32_t ah[2][4];
#pragma unroll
            for (int im = 0; im < 2; im++) {
                uint32_t off = ((a_row + im * 16) * ASTR + ks * 16 + a_koff) * 2;
                ldm_x4(ah[im], sAh + off);
            }
            uint32_t bh[4][4];
#pragma unroll
            for (int jn = 0; jn < 4; jn++) {
                uint32_t off = ((b_row + jn * 16) * ASTR + ks * 16 + b_koff) * 2;
                ldm_x4(bh[jn], sBh + off);
            }
#pragma unroll
            for (int im = 0; im < 2; im++)
#pragma unroll
                for (int jb = 0; jb < 8; jb++) {
                    const uint32_t* ph = bh[jb >> 1] + (jb & 1) * 2;
                    mma_f16(acc[im][jb], ah[im], ph);
                }
        }
        if (++buf >= 3) buf = 0;
    }

    int g = lane >> 2, t4 = lane & 3;
#pragma unroll
    for (int im = 0; im < 2; im++) {
        int oa = ot * 128 + warp_m * 32 + im * 16 + g;
        int ob = oa + 8;
        float scA = bng[oa] * rsqrtf(bnv[oa] + EPSV);
        float scB = bng[ob] * rsqrtf(bnv[ob] + EPSV);
        float mbA = bnm[oa], bbA = bnb[oa];
        float mbB = bnm[ob], bbB = bnb[ob];
        const float* xa = x + ((size_t)n * 256 + oa) * 1024;
        const float* xb = x + ((size_t)n * 256 + ob) * 1024;
        float* pa = out + ((size_t)n * 256 + oa) * 1024;
        float* pb = out + ((size_t)n * 256 + ob) * 1024;
#pragma unroll
        for (int jb = 0; jb < 8; jb++) {
            int l = lt * 128 + warp_n * 64 + jb * 8 + t4 * 2;
            float2 xva = *(const float2*)&xa[l];
            float2 xvb = *(const float2*)&xb[l];
            float2 ra, rb;
            ra.x = (acc[im][jb][0] - mbA) * scA + bbA + xva.x;
            ra.y = (acc[im][jb][1] - mbA) * scA + bbA + xva.y;
            rb.x = (acc[im][jb][2] - mbB) * scB + bbB + xvb.x;
            rb.y = (acc[im][jb][3] - mbB) * scB + bbB + xvb.y;
            *(float2*)&pa[l] = ra;
            *(float2*)&pb[l] = rb;
        }
    }
}

// ============================== launcher ====================================
extern "C" void kernel_launch(void* const* d_in, const int* in_sizes, int n_in,
                              void* d_out, int out_size) {
    const float* x    = (const float*)d_in[0];
    const float* wq   = (const float*)d_in[1];
    const float* wk   = (const float*)d_in[2];
    const float* g1   = (const float*)d_in[3];
    const float* be1  = (const float*)d_in[4];
    const float* w1   = (const float*)d_in[5];
    const float* b1   = (const float*)d_in[6];
    const float* w2   = (const float*)d_in[7];
    const float* b2   = (const float*)d_in[8];
    const float* g2   = (const float*)d_in[9];
    const float* be2  = (const float*)d_in[10];
    const float* wout = (const float*)d_in[11];
    const float* bng  = (const float*)d_in[12];
    const float* bnb  = (const float*)d_in[13];
    const float* bnm  = (const float*)d_in[14];
    const float* bnv  = (const float*)d_in[15];
    float* out = (float*)d_out;

    static bool attr_done = false;
    if (!attr_done) {
        cudaFuncSetAttribute(kA2, cudaFuncAttributeMaxDynamicSharedMemorySize,
                             3 * BUF_B);
        cudaFuncSetAttribute(kE_mma, cudaFuncAttributeMaxDynamicSharedMemorySize,
                             3 * BUF_B);
        cudaFuncSetAttribute(kD_mma, cudaFuncAttributeMaxDynamicSharedMemorySize,
                             KD_SMEM);
        attr_done = true;
    }

    kWV<<<384, 256>>>(wq, wk, wout);
    kT<<<dim3(8, 32, 32), dim3(32, 8)>>>(x);
    kA2<<<dim3(8, 2, 32), 256, 3 * BUF_B>>>();
    kB<<<dim3(32, 32, 2), 288>>>();
    kB2<<<32, 256>>>(g1, be1);
    kC<<<dim3(4, 72), 256>>>(w1);
    kC2<<<32, 256>>>(b1);
    kD_mma<<<1024, 256, KD_SMEM>>>(w2, b2);
    kD2<<<32, 256>>>();
    kE0<<<dim3(4, 32, 32), dim3(32, 8)>>>(g2, be2);
    kE_mma<<<dim3(8, 2, 32), 256, 3 * BUF_B>>>(bng, bnb, bnm, bnv, x, out);
}